// round 4
// baseline (speedup 1.0000x reference)
#include <cuda_runtime.h>
#include <math.h>

#define BGR   128
#define NND   64
#define KIN   320
#define HID   256
#define OUTD  128
#define EPG   2016
#define TOTE  (BGR*EPG)     // 258048
#define NODES (BGR*NND)     // 8192

// ---- scratch (device globals) ----
__device__ float  g_AGG[NODES*KIN];
__device__ float  g_H[NODES*HID];
__device__ float  g_Pm[NODES*OUTD];
__device__ float  g_Qm[NODES*OUTD];
__device__ float  g_Pv[NODES*OUTD];
__device__ float  g_Qv[NODES*OUTD];
__device__ float  g_pw[NODES];
__device__ float  g_qw[NODES];
__device__ float  g_z[TOTE];
__device__ float  g_sim[TOTE];
__device__ double g_sum;

// ---------------------------------------------------------------------------
__global__ void zero_kernel() { g_sum = 0.0; }

// Literal aggregation: agg[b,j,c] = (1/j) * sum_{i<j} X[b,i,c]; 0 at j==0.
// X = [topo | temp] per node.
__global__ void agg_kernel(const float* __restrict__ topo,
                           const float* __restrict__ temp) {
    int b = blockIdx.y;
    int c = blockIdx.x * 64 + threadIdx.x;
    if (c >= KIN) return;
    float run = 0.f;
    for (int j = 0; j < NND; j++) {
        g_AGG[((size_t)b * NND + j) * KIN + c] = (j == 0) ? 0.f : run / (float)j;
        float xv = (c < 64) ? topo[((size_t)b * NND + j) * 64 + c]
                            : temp[((size_t)b * NND + j) * 256 + (c - 64)];
        run += xv;
    }
}

// H[n,c] = relu( sum_k AGG[n,k] * W_gnn[k,c] + b_gnn[c] )
__global__ void h_kernel(const float* __restrict__ W, const float* __restrict__ bias) {
    int n = blockIdx.y;
    int c = blockIdx.x * 64 + threadIdx.x;   // grid.x = 4 -> c < 256
    const float* a = g_AGG + (size_t)n * KIN;
    float s = 0.f;
    for (int k = 0; k < KIN; k++) s = fmaf(a[k], W[k * HID + c], s);
    s += bias[c];
    g_H[(size_t)n * HID + c] = s > 0.f ? s : 0.f;
}

// Per-node head projections.
// Pm[n,c] = sum_{k<256} h[n,k] Wm[k,c]        (src half)
// Qm[n,c] = sum_{k<256} h[n,k] Wm[256+k,c]    (dst half); same for Wv.
__global__ void pq_kernel(const float* __restrict__ Wm, const float* __restrict__ Wv) {
    int n = blockIdx.y;
    int c = blockIdx.x * 64 + threadIdx.x;   // grid.x = 2 -> c < 128
    const float* h = g_H + (size_t)n * HID;
    float pm = 0.f, qm = 0.f, pv = 0.f, qv = 0.f;
    for (int k = 0; k < HID; k++) {
        float hv = h[k];
        pm = fmaf(hv, Wm[k * OUTD + c], pm);
        qm = fmaf(hv, Wm[(HID + k) * OUTD + c], qm);
        pv = fmaf(hv, Wv[k * OUTD + c], pv);
        qv = fmaf(hv, Wv[(HID + k) * OUTD + c], qv);
    }
    size_t o = (size_t)n * OUTD + c;
    g_Pm[o] = pm; g_Qm[o] = qm; g_Pv[o] = pv; g_Qv[o] = qv;
}

// Weight head: pw[n] = h[n].W_w[0:256], qw[n] = h[n].W_w[256:512]
__global__ void whead_kernel(const float* __restrict__ Ww) {
    int n = blockIdx.x * 256 + threadIdx.x;
    if (n >= NODES) return;
    const float* h = g_H + (size_t)n * HID;
    float pw = 0.f, qw = 0.f;
    for (int k = 0; k < HID; k++) {
        pw = fmaf(h[k], Ww[k], pw);
        qw = fmaf(h[k], Ww[HID + k], qw);
    }
    g_pw[n] = pw; g_qw[n] = qw;
}

// Per-edge: z and sim. Thread per edge.
__global__ void edge_kernel(const float* __restrict__ gum,
                            const float* __restrict__ bm,
                            const float* __restrict__ bv,
                            const float* __restrict__ bw) {
    int t = blockIdx.x * 256 + threadIdx.x;
    if (t >= TOTE) return;
    int b = t / EPG, e = t % EPG;
    // decode triu row-major rank e -> (i, j), i<j
    int i = 0, r = e;
    while (r >= NND - 1 - i) { r -= NND - 1 - i; i++; }
    int j = i + 1 + r;
    int ni = b * NND + i, nj = b * NND + j;

    float acc = 0.f;
    for (int c = 0; c < OUTD; c++) {
        float m  = g_Pm[(size_t)ni * OUTD + c] + g_Qm[(size_t)nj * OUTD + c] + bm[c];
        float xv = g_Pv[(size_t)ni * OUTD + c] + g_Qv[(size_t)nj * OUTD + c] + bv[c];
        float sp  = fmaxf(xv, 0.f) + log1pf(expf(-fabsf(xv)));  // softplus
        float var = sp + 1e-6f;                                  // variance
        acc += (m * m) / (var + 1e-8f);
    }
    g_sim[t] = expf(-0.5f * (acc * (1.f / OUTD)));

    float wl = g_pw[ni] + g_qw[nj] + bw[0];
    float w  = 1.f / (1.f + expf(-wl));
    float u  = gum[t];
    float gb = -logf(-logf(u));
    g_z[t]   = (w + gb) * 2.f;   // / TEMPERATURE (0.5)
}

// Global softmax denominator (double).
__global__ void sum_kernel() {
    __shared__ double sh[256];
    int t = blockIdx.x * 256 + threadIdx.x;
    double v = (t < TOTE) ? exp((double)g_z[t]) : 0.0;
    sh[threadIdx.x] = v;
    __syncthreads();
    for (int s = 128; s; s >>= 1) {
        if (threadIdx.x < s) sh[threadIdx.x] += sh[threadIdx.x + s];
        __syncthreads();
    }
    if (threadIdx.x == 0) atomicAdd(&g_sum, sh[0]);
}

// adj[b,i,j] = sim * exp(z)/sum at upper-tri, else 0.
__global__ void out_kernel(float* __restrict__ out) {
    int idx = blockIdx.x * 256 + threadIdx.x;    // < 524288
    int b = idx >> 12;
    int rem = idx & 4095;
    int i = rem >> 6, j = rem & 63;
    float val = 0.f;
    if (i < j) {
        int e = i * (NND - 1) - (i * (i - 1)) / 2 + (j - i - 1);
        int t = b * EPG + e;
        double p = exp((double)g_z[t]) / g_sum;
        val = (float)((double)g_sim[t] * p);
    }
    out[idx] = val;
}

// ---------------------------------------------------------------------------
extern "C" void kernel_launch(void* const* d_in, const int* in_sizes, int n_in,
                              void* d_out, int out_size) {
    // Resolve inputs by element count (robust to ordering). Ambiguous pairs
    // (65536: W_mean/W_var, 128: b_mean/b_var) resolved by first-occurrence.
    const float *x_topo = 0, *x_temp = 0, *gum = 0, *W_gnn = 0, *b_gnn = 0;
    const float *W_mean = 0, *b_mean = 0, *W_var = 0, *b_var = 0, *W_w = 0, *b_w = 0;
    for (int k = 0; k < n_in; k++) {
        const float* p = (const float*)d_in[k];
        switch (in_sizes[k]) {
            case 524288:  x_topo = p; break;
            case 2097152: x_temp = p; break;
            case 258048:  gum = p; break;
            case 81920:   W_gnn = p; break;
            case 256:     b_gnn = p; break;
            case 65536:   if (!W_mean) W_mean = p; else W_var = p; break;
            case 128:     if (!b_mean) b_mean = p; else b_var = p; break;
            case 512:     W_w = p; break;
            case 1:       b_w = p; break;
            default: break;
        }
    }
    float* out = (float*)d_out;

    zero_kernel<<<1, 1>>>();

    { dim3 g((KIN + 63) / 64, BGR); agg_kernel<<<g, 64>>>(x_topo, x_temp); }

    { dim3 g(HID / 64, NODES); h_kernel<<<g, 64>>>(W_gnn, b_gnn); }

    { dim3 g(OUTD / 64, NODES); pq_kernel<<<g, 64>>>(W_mean, W_var); }

    whead_kernel<<<NODES / 256, 256>>>(W_w);

    edge_kernel<<<(TOTE + 255) / 256, 256>>>(gum, b_mean, b_var, b_w);

    sum_kernel<<<(TOTE + 255) / 256, 256>>>();

    out_kernel<<<(BGR * NND * NND) / 256, 256>>>(out);
}

// round 9
// speedup vs baseline: 1.5471x; 1.5471x over previous
#include <cuda_runtime.h>
#include <math.h>

#define BGR   128
#define NND   64
#define KIN   320
#define HID   256
#define OUTD  128
#define EPG   2016
#define TOTE  (BGR*EPG)     // 258048
#define NODES (BGR*NND)     // 8192

// ---- scratch (device globals; referenced ONLY by name inside device code) ----
__device__ float  g_AGG[NODES*KIN];
__device__ float  g_H[NODES*HID];
__device__ float  g_WB[HID*512];      // packed head weights [256,512]
__device__ float  g_PQ[NODES*512];    // per-node [Pm|Pv|Qm|Qv]
__device__ float  g_pw[NODES];
__device__ float  g_qw[NODES];
__device__ float  g_prod[TOTE];       // sim * exp(z)
__device__ double g_sum;
__device__ float  g_inv;
__device__ int    g_eij[EPG];

// ---------------------------------------------------------------------------
// f32x2 helpers (packed fp32 pipe; IEEE-identical per lane)
// ---------------------------------------------------------------------------
__device__ __forceinline__ unsigned long long pack2(float lo, float hi) {
    unsigned long long r;
    asm("mov.b64 %0, {%1, %2};" : "=l"(r) : "f"(lo), "f"(hi));
    return r;
}
__device__ __forceinline__ unsigned long long ffma2(unsigned long long a,
                                                    unsigned long long b,
                                                    unsigned long long c) {
    unsigned long long d;
    asm("fma.rn.f32x2 %0, %1, %2, %3;" : "=l"(d) : "l"(a), "l"(b), "l"(c));
    return d;
}
__device__ __forceinline__ void unpack2(unsigned long long v, float& lo, float& hi) {
    asm("mov.b64 {%0, %1}, %2;" : "=f"(lo), "=f"(hi) : "l"(v));
}

// ---------------------------------------------------------------------------
// Setup: zero sum, edge table, pack WB.
//  c<128 -> Wm[k,c] (Pm)       128..255 -> Wv[k,c-128] (Pv)
//  256..383 -> Wm[256+k,·] (Qm) 384..511 -> Wv[256+k,·] (Qv)
// ---------------------------------------------------------------------------
__global__ void setup_kernel(const float* __restrict__ Wm, const float* __restrict__ Wv) {
    int tid = blockIdx.x * blockDim.x + threadIdx.x;   // 131072 threads
    if (tid == 0) g_sum = 0.0;
    if (tid < EPG) {
        int e = tid, i = 0;
        while (e >= (NND - 1 - i)) { e -= (NND - 1 - i); i++; }
        g_eij[tid] = (i << 8) | (i + 1 + e);
    }
    int k = tid >> 9;
    int c = tid & 511;
    float v;
    if      (c < 128) v = Wm[k * 128 + c];
    else if (c < 256) v = Wv[k * 128 + (c - 128)];
    else if (c < 384) v = Wm[(256 + k) * 128 + (c - 256)];
    else              v = Wv[(256 + k) * 128 + (c - 384)];
    g_WB[tid] = v;
}

// ---------------------------------------------------------------------------
// Literal aggregation (R4 verbatim; writes g_AGG by name)
// ---------------------------------------------------------------------------
__global__ void agg_kernel(const float* __restrict__ topo,
                           const float* __restrict__ temp) {
    int b = blockIdx.y;
    int c = blockIdx.x * 64 + threadIdx.x;
    if (c >= KIN) return;
    float run = 0.f;
    for (int j = 0; j < NND; j++) {
        g_AGG[((size_t)b * NND + j) * KIN + c] = (j == 0) ? 0.f : run / (float)j;
        float xv = (c < 64) ? topo[((size_t)b * NND + j) * 64 + c]
                            : temp[((size_t)b * NND + j) * 256 + (c - 64)];
        run += xv;
    }
}

// ---------------------------------------------------------------------------
// Tiled SGEMM body (f32x2): C = A[M,K] @ B[K,N] (+bias, relu optional).
// Called ONLY from device wrappers so global-array pointers are device-valid.
// BM=BN=128, BK=16, 256 thr, 8x8/thread.
// ---------------------------------------------------------------------------
template <int RELU>
__device__ __forceinline__
void sgemm_body(const float* __restrict__ A, const float* __restrict__ B,
                const float* __restrict__ bias, float* __restrict__ C,
                int M, int N, int K) {
    __shared__ float As[16][128];
    __shared__ float Bs[16][128];
    const int tid = threadIdx.x;
    const int m0 = blockIdx.y * 128;
    const int n0 = blockIdx.x * 128;
    const int tx = tid & 15;
    const int ty = tid >> 4;

    unsigned long long acc2[4][8];
#pragma unroll
    for (int p = 0; p < 4; p++)
#pragma unroll
        for (int v = 0; v < 8; v++) acc2[p][v] = 0ull;

    for (int k0 = 0; k0 < K; k0 += 16) {
#pragma unroll
        for (int q = 0; q < 2; q++) {
            int idx = tid + q * 256;
            int row = idx >> 2;
            int c4  = (idx & 3) * 4;
            float4 v = *reinterpret_cast<const float4*>(A + (size_t)(m0 + row) * K + k0 + c4);
            As[c4 + 0][row] = v.x;
            As[c4 + 1][row] = v.y;
            As[c4 + 2][row] = v.z;
            As[c4 + 3][row] = v.w;
        }
#pragma unroll
        for (int q = 0; q < 2; q++) {
            int idx = tid + q * 256;
            int row = idx >> 5;
            int c4  = (idx & 31) * 4;
            *reinterpret_cast<float4*>(&Bs[row][c4]) =
                *reinterpret_cast<const float4*>(B + (size_t)(k0 + row) * N + n0 + c4);
        }
        __syncthreads();

#pragma unroll
        for (int k = 0; k < 16; k++) {
            const unsigned long long* ap =
                reinterpret_cast<const unsigned long long*>(&As[k][ty * 8]);
            unsigned long long A2[4] = {ap[0], ap[1], ap[2], ap[3]};
            float4 b0 = *reinterpret_cast<const float4*>(&Bs[k][tx * 8]);
            float4 b1 = *reinterpret_cast<const float4*>(&Bs[k][tx * 8 + 4]);
            unsigned long long B2[8] = {
                pack2(b0.x, b0.x), pack2(b0.y, b0.y), pack2(b0.z, b0.z), pack2(b0.w, b0.w),
                pack2(b1.x, b1.x), pack2(b1.y, b1.y), pack2(b1.z, b1.z), pack2(b1.w, b1.w)
            };
#pragma unroll
            for (int p = 0; p < 4; p++)
#pragma unroll
                for (int v = 0; v < 8; v++)
                    acc2[p][v] = ffma2(A2[p], B2[v], acc2[p][v]);
        }
        __syncthreads();
    }

    float bv8[8];
#pragma unroll
    for (int v = 0; v < 8; v++) bv8[v] = bias ? bias[n0 + tx * 8 + v] : 0.f;

#pragma unroll
    for (int p = 0; p < 4; p++) {
        float lo[8], hi[8];
#pragma unroll
        for (int v = 0; v < 8; v++) unpack2(acc2[p][v], lo[v], hi[v]);
#pragma unroll
        for (int half = 0; half < 2; half++) {
            float* src = half ? hi : lo;
            int m = m0 + ty * 8 + 2 * p + half;
            float o[8];
#pragma unroll
            for (int v = 0; v < 8; v++) {
                float val = src[v] + bv8[v];
                if (RELU) val = val > 0.f ? val : 0.f;
                o[v] = val;
            }
            *reinterpret_cast<float4*>(C + (size_t)m * N + n0 + tx * 8) =
                make_float4(o[0], o[1], o[2], o[3]);
            *reinterpret_cast<float4*>(C + (size_t)m * N + n0 + tx * 8 + 4) =
                make_float4(o[4], o[5], o[6], o[7]);
        }
    }
}

// Wrappers: device globals bound BY NAME here (valid device addresses).
__global__ __launch_bounds__(256, 2)
void sgemm1_kernel(const float* __restrict__ Wg, const float* __restrict__ bg) {
    sgemm_body<1>(g_AGG, Wg, bg, g_H, NODES, HID, KIN);
}
__global__ __launch_bounds__(256, 2)
void sgemm2_kernel() {
    sgemm_body<0>(g_H, g_WB, nullptr, g_PQ, NODES, 512, HID);
}

// ---------------------------------------------------------------------------
// Weight head (R4 verbatim)
// ---------------------------------------------------------------------------
__global__ void whead_kernel(const float* __restrict__ Ww) {
    int n = blockIdx.x * 256 + threadIdx.x;
    if (n >= NODES) return;
    const float* h = g_H + (size_t)n * HID;
    float pw = 0.f, qw = 0.f;
    for (int k = 0; k < HID; k++) {
        pw = fmaf(h[k], Ww[k], pw);
        qw = fmaf(h[k], Ww[HID + k], qw);
    }
    g_pw[n] = pw; g_qw[n] = qw;
}

// ---------------------------------------------------------------------------
// Edge kernel: CTA per graph, 128KB PQ slab in dyn smem, warp per edge.
// Math identical to passing R4. Fused double softmax-sum.
// ---------------------------------------------------------------------------
__global__ void edge_kernel(const float* __restrict__ gum,
                            const float* __restrict__ bm,
                            const float* __restrict__ bv,
                            const float* __restrict__ bw) {
    extern __shared__ float s_pq[];     // 64*512
    __shared__ float s_pw[NND], s_qw[NND], s_bm[OUTD], s_bv[OUTD];
    __shared__ int   s_eij[EPG];

    const int b = blockIdx.x;
    const int tid = threadIdx.x;

    const float4* src = reinterpret_cast<const float4*>(g_PQ + (size_t)b * NND * 512);
    float4* dst = reinterpret_cast<float4*>(s_pq);
    for (int i = tid; i < NND * 512 / 4; i += 256) dst[i] = src[i];
    if (tid < NND)  { s_pw[tid] = g_pw[b * NND + tid]; s_qw[tid] = g_qw[b * NND + tid]; }
    if (tid < OUTD) { s_bm[tid] = bm[tid]; s_bv[tid] = bv[tid]; }
    for (int i = tid; i < EPG; i += 256) s_eij[i] = g_eij[i];
    __syncthreads();

    const float bwv = bw[0];
    const int warp = tid >> 5, lane = tid & 31;
    double ssum = 0.0;

    for (int e = warp; e < EPG; e += 8) {
        int ij = s_eij[e];
        int i = ij >> 8, j = ij & 255;
        const float* P = s_pq + i * 512;
        const float* Q = s_pq + j * 512;
        float acc = 0.f;
#pragma unroll
        for (int t = 0; t < 4; t++) {
            int k = lane + 32 * t;
            float m   = P[k]       + Q[256 + k] + s_bm[k];
            float xv  = P[128 + k] + Q[384 + k] + s_bv[k];
            float sp  = fmaxf(xv, 0.f) + log1pf(expf(-fabsf(xv)));
            float var = sp + 1e-6f;
            acc += (m * m) / (var + 1e-8f);
        }
#pragma unroll
        for (int o = 16; o; o >>= 1) acc += __shfl_xor_sync(0xFFFFFFFFu, acc, o);

        if (lane == 0) {
            float sim = expf(-0.5f * (acc * (1.f / OUTD)));
            float wl  = s_pw[i] + s_qw[j] + bwv;
            float w   = 1.f / (1.f + expf(-wl));
            float u   = gum[b * EPG + e];
            float gb  = -logf(-logf(u));
            float z   = (w + gb) * 2.f;     // / TEMPERATURE (0.5)
            float s   = expf(z);
            g_prod[b * EPG + e] = sim * s;
            ssum += (double)s;
        }
    }
    if (lane == 0) atomicAdd(&g_sum, ssum);
}

__global__ void inv_kernel() { g_inv = (float)(1.0 / g_sum); }

__global__ void out_kernel(float* __restrict__ out) {
    int idx = blockIdx.x * 256 + threadIdx.x;
    int b = idx >> 12;
    int rem = idx & 4095;
    int i = rem >> 6, j = rem & 63;
    float val = 0.f;
    if (i < j) {
        int e = i * (NND - 1) - (i * (i - 1)) / 2 + (j - i - 1);
        val = g_prod[b * EPG + e] * g_inv;
    }
    out[idx] = val;
}

// ---------------------------------------------------------------------------
extern "C" void kernel_launch(void* const* d_in, const int* in_sizes, int n_in,
                              void* d_out, int out_size) {
    // Size-based binding. NOTE: no __device__ global is ever passed as an arg.
    const float *x_topo = 0, *x_temp = 0, *gum = 0, *W_gnn = 0, *b_gnn = 0;
    const float *W_mean = 0, *b_mean = 0, *W_var = 0, *b_var = 0, *W_w = 0, *b_w = 0;
    for (int k = 0; k < n_in; k++) {
        const float* p = (const float*)d_in[k];
        switch (in_sizes[k]) {
            case 524288:  x_topo = p; break;
            case 2097152: x_temp = p; break;
            case 258048:  gum = p; break;
            case 81920:   W_gnn = p; break;
            case 256:     b_gnn = p; break;
            case 65536:   if (!W_mean) W_mean = p; else W_var = p; break;
            case 128:     if (!b_mean) b_mean = p; else b_var = p; break;
            case 512:     W_w = p; break;
            case 1:       b_w = p; break;
            default: break;
        }
    }
    float* out = (float*)d_out;

    cudaFuncSetAttribute(edge_kernel, cudaFuncAttributeMaxDynamicSharedMemorySize, 131072);

    setup_kernel<<<512, 256>>>(W_mean, W_var);

    { dim3 g((KIN + 63) / 64, BGR); agg_kernel<<<g, 64>>>(x_topo, x_temp); }

    { dim3 g(HID / 128, NODES / 128); sgemm1_kernel<<<g, 256>>>(W_gnn, b_gnn); }

    { dim3 g(512 / 128, NODES / 128); sgemm2_kernel<<<g, 256>>>(); }

    whead_kernel<<<NODES / 256, 256>>>(W_w);

    edge_kernel<<<BGR, 256, 131072>>>(gum, b_mean, b_var, b_w);

    inv_kernel<<<1, 1>>>();

    out_kernel<<<(BGR * NND * NND) / 256, 256>>>(out);
}

// round 10
// speedup vs baseline: 2.3358x; 1.5098x over previous
#include <cuda_runtime.h>
#include <math.h>

#define BGR   128
#define NND   64
#define KIN   320
#define HID   256
#define OUTD  128
#define EPG   2016
#define TOTE  (BGR*EPG)     // 258048
#define NODES (BGR*NND)     // 8192

// ---- scratch (device globals; referenced ONLY by name inside device code) ----
__device__ float  g_AGG[NODES*KIN];
__device__ float  g_H[NODES*HID];
__device__ float  g_WB[HID*512];
__device__ float  g_PQ[NODES*512];
__device__ float  g_pw[NODES];
__device__ float  g_qw[NODES];
__device__ float  g_prod[TOTE];
__device__ double g_sum;
__device__ float  g_inv;
__device__ int    g_eij[EPG];

// ---------------------------------------------------------------------------
// f32x2 helpers
// ---------------------------------------------------------------------------
__device__ __forceinline__ unsigned long long pack2(float lo, float hi) {
    unsigned long long r;
    asm("mov.b64 %0, {%1, %2};" : "=l"(r) : "f"(lo), "f"(hi));
    return r;
}
__device__ __forceinline__ unsigned long long ffma2(unsigned long long a,
                                                    unsigned long long b,
                                                    unsigned long long c) {
    unsigned long long d;
    asm("fma.rn.f32x2 %0, %1, %2, %3;" : "=l"(d) : "l"(a), "l"(b), "l"(c));
    return d;
}
__device__ __forceinline__ void unpack2(unsigned long long v, float& lo, float& hi) {
    asm("mov.b64 {%0, %1}, %2;" : "=f"(lo), "=f"(hi) : "l"(v));
}

// ---------------------------------------------------------------------------
// Setup: zero sum, edge table, pack WB.
// ---------------------------------------------------------------------------
__global__ void setup_kernel(const float* __restrict__ Wm, const float* __restrict__ Wv) {
    int tid = blockIdx.x * blockDim.x + threadIdx.x;   // 131072 threads
    if (tid == 0) g_sum = 0.0;
    if (tid < EPG) {
        int e = tid, i = 0;
        while (e >= (NND - 1 - i)) { e -= (NND - 1 - i); i++; }
        g_eij[tid] = (i << 8) | (i + 1 + e);
    }
    int k = tid >> 9;
    int c = tid & 511;
    float v;
    if      (c < 128) v = Wm[k * 128 + c];
    else if (c < 256) v = Wv[k * 128 + (c - 128)];
    else if (c < 384) v = Wm[(256 + k) * 128 + (c - 256)];
    else              v = Wv[(256 + k) * 128 + (c - 384)];
    g_WB[tid] = v;
}

// ---------------------------------------------------------------------------
// Literal aggregation
// ---------------------------------------------------------------------------
__global__ void agg_kernel(const float* __restrict__ topo,
                           const float* __restrict__ temp) {
    int b = blockIdx.y;
    int c = blockIdx.x * 64 + threadIdx.x;
    if (c >= KIN) return;
    float run = 0.f;
#pragma unroll 8
    for (int j = 0; j < NND; j++) {
        g_AGG[((size_t)b * NND + j) * KIN + c] = (j == 0) ? 0.f : run / (float)j;
        float xv = (c < 64) ? topo[((size_t)b * NND + j) * 64 + c]
                            : temp[((size_t)b * NND + j) * 256 + (c - 64)];
        run += xv;
    }
}

// ---------------------------------------------------------------------------
// Double-buffered tiled SGEMM (f32x2), register prefetch.
// C = A[M,K] @ B[K,N] (+bias, relu). BM=BN=128, BK=16, 256 thr, 8x8/thread.
// ---------------------------------------------------------------------------
template <int RELU>
__device__ __forceinline__
void sgemm_body(const float* __restrict__ A, const float* __restrict__ B,
                const float* __restrict__ bias, float* __restrict__ C,
                int M, int N, int K) {
    __shared__ float As[2][16][128];
    __shared__ float Bs[2][16][128];
    const int tid = threadIdx.x;
    const int m0 = blockIdx.y * 128;
    const int n0 = blockIdx.x * 128;
    const int tx = tid & 15;
    const int ty = tid >> 4;

    // per-thread load coordinates (fixed across tiles)
    const int aRow0 = (tid)        >> 2, aC40 = ((tid)        & 3) * 4;
    const int aRow1 = (tid + 256)  >> 2, aC41 = ((tid + 256)  & 3) * 4;
    const int bRow0 = (tid)        >> 5, bC40 = ((tid)        & 31) * 4;
    const int bRow1 = (tid + 256)  >> 5, bC41 = ((tid + 256)  & 31) * 4;

    float4 pa0, pa1, pb0, pb1;

    auto loadTile = [&](int k0) {
        pa0 = *reinterpret_cast<const float4*>(A + (size_t)(m0 + aRow0) * K + k0 + aC40);
        pa1 = *reinterpret_cast<const float4*>(A + (size_t)(m0 + aRow1) * K + k0 + aC41);
        pb0 = *reinterpret_cast<const float4*>(B + (size_t)(k0 + bRow0) * N + n0 + bC40);
        pb1 = *reinterpret_cast<const float4*>(B + (size_t)(k0 + bRow1) * N + n0 + bC41);
    };
    auto storeTile = [&](int buf) {
        As[buf][aC40 + 0][aRow0] = pa0.x;
        As[buf][aC40 + 1][aRow0] = pa0.y;
        As[buf][aC40 + 2][aRow0] = pa0.z;
        As[buf][aC40 + 3][aRow0] = pa0.w;
        As[buf][aC41 + 0][aRow1] = pa1.x;
        As[buf][aC41 + 1][aRow1] = pa1.y;
        As[buf][aC41 + 2][aRow1] = pa1.z;
        As[buf][aC41 + 3][aRow1] = pa1.w;
        *reinterpret_cast<float4*>(&Bs[buf][bRow0][bC40]) = pb0;
        *reinterpret_cast<float4*>(&Bs[buf][bRow1][bC41]) = pb1;
    };

    unsigned long long acc2[4][8];
#pragma unroll
    for (int p = 0; p < 4; p++)
#pragma unroll
        for (int v = 0; v < 8; v++) acc2[p][v] = 0ull;

    const int T = K / 16;
    int buf = 0;
    loadTile(0);
    storeTile(0);
    __syncthreads();

    for (int t = 0; t < T; t++) {
        if (t + 1 < T) loadTile((t + 1) * 16);   // LDGs in flight during compute

#pragma unroll
        for (int k = 0; k < 16; k++) {
            const unsigned long long* ap =
                reinterpret_cast<const unsigned long long*>(&As[buf][k][ty * 8]);
            unsigned long long A2[4] = {ap[0], ap[1], ap[2], ap[3]};
            float4 b0 = *reinterpret_cast<const float4*>(&Bs[buf][k][tx * 8]);
            float4 b1 = *reinterpret_cast<const float4*>(&Bs[buf][k][tx * 8 + 4]);
            unsigned long long B2[8] = {
                pack2(b0.x, b0.x), pack2(b0.y, b0.y), pack2(b0.z, b0.z), pack2(b0.w, b0.w),
                pack2(b1.x, b1.x), pack2(b1.y, b1.y), pack2(b1.z, b1.z), pack2(b1.w, b1.w)
            };
#pragma unroll
            for (int p = 0; p < 4; p++)
#pragma unroll
                for (int v = 0; v < 8; v++)
                    acc2[p][v] = ffma2(A2[p], B2[v], acc2[p][v]);
        }

        if (t + 1 < T) {
            storeTile(buf ^ 1);
            __syncthreads();
            buf ^= 1;
        }
    }

    float bv8[8];
#pragma unroll
    for (int v = 0; v < 8; v++) bv8[v] = bias ? bias[n0 + tx * 8 + v] : 0.f;

#pragma unroll
    for (int p = 0; p < 4; p++) {
        float lo[8], hi[8];
#pragma unroll
        for (int v = 0; v < 8; v++) unpack2(acc2[p][v], lo[v], hi[v]);
#pragma unroll
        for (int half = 0; half < 2; half++) {
            float* src = half ? hi : lo;
            int m = m0 + ty * 8 + 2 * p + half;
            float o[8];
#pragma unroll
            for (int v = 0; v < 8; v++) {
                float val = src[v] + bv8[v];
                if (RELU) val = val > 0.f ? val : 0.f;
                o[v] = val;
            }
            *reinterpret_cast<float4*>(C + (size_t)m * N + n0 + tx * 8) =
                make_float4(o[0], o[1], o[2], o[3]);
            *reinterpret_cast<float4*>(C + (size_t)m * N + n0 + tx * 8 + 4) =
                make_float4(o[4], o[5], o[6], o[7]);
        }
    }
}

__global__ __launch_bounds__(256, 2)
void sgemm1_kernel(const float* __restrict__ Wg, const float* __restrict__ bg) {
    sgemm_body<1>(g_AGG, Wg, bg, g_H, NODES, HID, KIN);
}
__global__ __launch_bounds__(256, 2)
void sgemm2_kernel() {
    sgemm_body<0>(g_H, g_WB, nullptr, g_PQ, NODES, 512, HID);
}

// ---------------------------------------------------------------------------
// Weight head: warp per node, coalesced lane-strided loads + shfl reduce.
// ---------------------------------------------------------------------------
__global__ void whead_kernel(const float* __restrict__ Ww) {
    int warp = (blockIdx.x * blockDim.x + threadIdx.x) >> 5;
    int lane = threadIdx.x & 31;
    if (warp >= NODES) return;
    const float* h = g_H + (size_t)warp * HID;
    float pw = 0.f, qw = 0.f;
#pragma unroll
    for (int t = 0; t < 8; t++) {
        int k = lane + 32 * t;
        float hv = h[k];
        pw = fmaf(hv, Ww[k], pw);
        qw = fmaf(hv, Ww[HID + k], qw);
    }
#pragma unroll
    for (int o = 16; o; o >>= 1) {
        pw += __shfl_xor_sync(0xFFFFFFFFu, pw, o);
        qw += __shfl_xor_sync(0xFFFFFFFFu, qw, o);
    }
    if (lane == 0) { g_pw[warp] = pw; g_qw[warp] = qw; }
}

// ---------------------------------------------------------------------------
// Edge kernel: CTA per graph, 512 threads (16 warps), 128KB PQ slab in smem.
// Warp per edge, lanes split 128 dims. Fused double softmax-sum.
// ---------------------------------------------------------------------------
__global__ __launch_bounds__(512, 1)
void edge_kernel(const float* __restrict__ gum,
                 const float* __restrict__ bm,
                 const float* __restrict__ bv,
                 const float* __restrict__ bw) {
    extern __shared__ float s_pq[];     // 64*512
    __shared__ float s_pw[NND], s_qw[NND], s_bm[OUTD], s_bv[OUTD];
    __shared__ int   s_eij[EPG];

    const int b = blockIdx.x;
    const int tid = threadIdx.x;

    const float4* src = reinterpret_cast<const float4*>(g_PQ + (size_t)b * NND * 512);
    float4* dst = reinterpret_cast<float4*>(s_pq);
    for (int i = tid; i < NND * 512 / 4; i += 512) dst[i] = src[i];
    if (tid < NND)  { s_pw[tid] = g_pw[b * NND + tid]; s_qw[tid] = g_qw[b * NND + tid]; }
    if (tid >= 512 - OUTD) { int c = tid - (512 - OUTD); s_bm[c] = bm[c]; s_bv[c] = bv[c]; }
    for (int i = tid; i < EPG; i += 512) s_eij[i] = g_eij[i];
    __syncthreads();

    const float bwv = bw[0];
    const int warp = tid >> 5, lane = tid & 31;
    double ssum = 0.0;

    for (int e = warp; e < EPG; e += 16) {
        int ij = s_eij[e];
        int i = ij >> 8, j = ij & 255;
        const float* P = s_pq + i * 512;
        const float* Q = s_pq + j * 512;
        float acc = 0.f;
#pragma unroll
        for (int t = 0; t < 4; t++) {
            int k = lane + 32 * t;
            float m   = P[k]       + Q[256 + k] + s_bm[k];
            float xv  = P[128 + k] + Q[384 + k] + s_bv[k];
            float sp  = fmaxf(xv, 0.f) + log1pf(expf(-fabsf(xv)));
            float var = sp + 1e-6f;
            acc += (m * m) / (var + 1e-8f);
        }
#pragma unroll
        for (int o = 16; o; o >>= 1) acc += __shfl_xor_sync(0xFFFFFFFFu, acc, o);

        if (lane == 0) {
            float sim = expf(-0.5f * (acc * (1.f / OUTD)));
            float wl  = s_pw[i] + s_qw[j] + bwv;
            float w   = 1.f / (1.f + expf(-wl));
            float u   = gum[b * EPG + e];
            float gb  = -logf(-logf(u));
            float z   = (w + gb) * 2.f;     // / TEMPERATURE (0.5)
            float s   = expf(z);
            g_prod[b * EPG + e] = sim * s;
            ssum += (double)s;
        }
    }
    if (lane == 0) atomicAdd(&g_sum, ssum);
}

__global__ void inv_kernel() { g_inv = (float)(1.0 / g_sum); }

__global__ void out_kernel(float* __restrict__ out) {
    int idx = blockIdx.x * 256 + threadIdx.x;
    int b = idx >> 12;
    int rem = idx & 4095;
    int i = rem >> 6, j = rem & 63;
    float val = 0.f;
    if (i < j) {
        int e = i * (NND - 1) - (i * (i - 1)) / 2 + (j - i - 1);
        val = g_prod[b * EPG + e] * g_inv;
    }
    out[idx] = val;
}

// ---------------------------------------------------------------------------
extern "C" void kernel_launch(void* const* d_in, const int* in_sizes, int n_in,
                              void* d_out, int out_size) {
    // Size-based binding. No __device__ global is ever passed as an arg.
    const float *x_topo = 0, *x_temp = 0, *gum = 0, *W_gnn = 0, *b_gnn = 0;
    const float *W_mean = 0, *b_mean = 0, *W_var = 0, *b_var = 0, *W_w = 0, *b_w = 0;
    for (int k = 0; k < n_in; k++) {
        const float* p = (const float*)d_in[k];
        switch (in_sizes[k]) {
            case 524288:  x_topo = p; break;
            case 2097152: x_temp = p; break;
            case 258048:  gum = p; break;
            case 81920:   W_gnn = p; break;
            case 256:     b_gnn = p; break;
            case 65536:   if (!W_mean) W_mean = p; else W_var = p; break;
            case 128:     if (!b_mean) b_mean = p; else b_var = p; break;
            case 512:     W_w = p; break;
            case 1:       b_w = p; break;
            default: break;
        }
    }
    float* out = (float*)d_out;

    cudaFuncSetAttribute(edge_kernel, cudaFuncAttributeMaxDynamicSharedMemorySize, 131072);

    setup_kernel<<<512, 256>>>(W_mean, W_var);

    { dim3 g((KIN + 63) / 64, BGR); agg_kernel<<<g, 64>>>(x_topo, x_temp); }

    { dim3 g(HID / 128, NODES / 128); sgemm1_kernel<<<g, 256>>>(W_gnn, b_gnn); }

    { dim3 g(512 / 128, NODES / 128); sgemm2_kernel<<<g, 256>>>(); }

    whead_kernel<<<NODES / 8, 256>>>(W_w);

    edge_kernel<<<BGR, 512, 131072>>>(gum, b_mean, b_var, b_w);

    inv_kernel<<<1, 1>>>();

    out_kernel<<<(BGR * NND * NND) / 256, 256>>>(out);
}

// round 11
// speedup vs baseline: 2.3558x; 1.0086x over previous
#include <cuda_runtime.h>
#include <math.h>

#define BGR   128
#define NND   64
#define KIN   320
#define HID   256
#define OUTD  128
#define EPG   2016
#define TOTE  (BGR*EPG)     // 258048
#define NODES (BGR*NND)     // 8192

// ---- scratch (device globals; referenced ONLY by name inside device code) ----
__device__ float  g_S[NODES*HID];     // X @ W_gnn (pre-aggregation)
__device__ float  g_H[NODES*HID];     // relu(prefix-mean(S) + b)
__device__ float  g_WB[HID*512];
__device__ float  g_PQ[NODES*512];
__device__ float  g_pw[NODES];
__device__ float  g_qw[NODES];
__device__ float  g_prod[TOTE];
__device__ double g_sum;
__device__ float  g_inv;
__device__ int    g_eij[EPG];

// ---------------------------------------------------------------------------
// f32x2 helpers
// ---------------------------------------------------------------------------
__device__ __forceinline__ unsigned long long pack2(float lo, float hi) {
    unsigned long long r;
    asm("mov.b64 %0, {%1, %2};" : "=l"(r) : "f"(lo), "f"(hi));
    return r;
}
__device__ __forceinline__ unsigned long long ffma2(unsigned long long a,
                                                    unsigned long long b,
                                                    unsigned long long c) {
    unsigned long long d;
    asm("fma.rn.f32x2 %0, %1, %2, %3;" : "=l"(d) : "l"(a), "l"(b), "l"(c));
    return d;
}
__device__ __forceinline__ void unpack2(unsigned long long v, float& lo, float& hi) {
    asm("mov.b64 {%0, %1}, %2;" : "=f"(lo), "=f"(hi) : "l"(v));
}

// ---------------------------------------------------------------------------
// Setup: zero sum, edge table, pack WB.
// ---------------------------------------------------------------------------
__global__ void setup_kernel(const float* __restrict__ Wm, const float* __restrict__ Wv) {
    int tid = blockIdx.x * blockDim.x + threadIdx.x;   // 131072 threads
    if (tid == 0) g_sum = 0.0;
    if (tid < EPG) {
        int e = tid, i = 0;
        while (e >= (NND - 1 - i)) { e -= (NND - 1 - i); i++; }
        g_eij[tid] = (i << 8) | (i + 1 + e);
    }
    int k = tid >> 9;
    int c = tid & 511;
    float v;
    if      (c < 128) v = Wm[k * 128 + c];
    else if (c < 256) v = Wv[k * 128 + (c - 128)];
    else if (c < 384) v = Wm[(256 + k) * 128 + (c - 256)];
    else              v = Wv[(256 + k) * 128 + (c - 384)];
    g_WB[tid] = v;
}

// ---------------------------------------------------------------------------
// Double-buffered tiled SGEMM (f32x2), register prefetch.
// BM=64, BN=128, BK=16, 256 threads, per-thread 4 rows x 8 cols.
// CONCAT=1: A is virtual [topo|temp] (K=320; col<64 topo, else temp).
// Tiles never straddle the 64-boundary (BK=16 | 64).
// ---------------------------------------------------------------------------
template <int RELU, int CONCAT>
__device__ __forceinline__
void sgemm_body(const float* __restrict__ A, const float* __restrict__ A2,
                const float* __restrict__ B,
                const float* __restrict__ bias, float* __restrict__ C,
                int M, int N, int K) {
    __shared__ float As[2][16][64];
    __shared__ float Bs[2][16][128];
    const int tid = threadIdx.x;
    const int m0 = blockIdx.y * 64;
    const int n0 = blockIdx.x * 128;
    const int tx = tid & 15;        // col group: 8 cols
    const int ty = tid >> 4;        // row group: 4 rows

    // A: 64x16 = 1024 floats -> 1 float4/thread
    const int aRow = tid >> 2, aC4 = (tid & 3) * 4;
    // B: 16x128 = 2048 floats -> 2 float4/thread
    const int bRow0 = tid >> 5, bRow1 = (tid >> 5) + 8;
    const int bC4 = (tid & 31) * 4;

    float4 pa, pb0, pb1;

    auto loadTile = [&](int k0) {
        if (CONCAT) {
            int kk = k0 + aC4;
            if (kk < 64)
                pa = *reinterpret_cast<const float4*>(A  + (size_t)(m0 + aRow) * 64  + kk);
            else
                pa = *reinterpret_cast<const float4*>(A2 + (size_t)(m0 + aRow) * 256 + (kk - 64));
        } else {
            pa = *reinterpret_cast<const float4*>(A + (size_t)(m0 + aRow) * K + k0 + aC4);
        }
        pb0 = *reinterpret_cast<const float4*>(B + (size_t)(k0 + bRow0) * N + n0 + bC4);
        pb1 = *reinterpret_cast<const float4*>(B + (size_t)(k0 + bRow1) * N + n0 + bC4);
    };
    auto storeTile = [&](int buf) {
        As[buf][aC4 + 0][aRow] = pa.x;
        As[buf][aC4 + 1][aRow] = pa.y;
        As[buf][aC4 + 2][aRow] = pa.z;
        As[buf][aC4 + 3][aRow] = pa.w;
        *reinterpret_cast<float4*>(&Bs[buf][bRow0][bC4]) = pb0;
        *reinterpret_cast<float4*>(&Bs[buf][bRow1][bC4]) = pb1;
    };

    unsigned long long acc2[2][8];   // 2 row-pairs x 8 cols
#pragma unroll
    for (int p = 0; p < 2; p++)
#pragma unroll
        for (int v = 0; v < 8; v++) acc2[p][v] = 0ull;

    const int T = K / 16;
    int buf = 0;
    loadTile(0);
    storeTile(0);
    __syncthreads();

    for (int t = 0; t < T; t++) {
        if (t + 1 < T) loadTile((t + 1) * 16);

#pragma unroll
        for (int k = 0; k < 16; k++) {
            const unsigned long long* ap =
                reinterpret_cast<const unsigned long long*>(&As[buf][k][ty * 4]);
            unsigned long long A2r[2] = {ap[0], ap[1]};
            float4 b0 = *reinterpret_cast<const float4*>(&Bs[buf][k][tx * 8]);
            float4 b1 = *reinterpret_cast<const float4*>(&Bs[buf][k][tx * 8 + 4]);
            unsigned long long B2[8] = {
                pack2(b0.x, b0.x), pack2(b0.y, b0.y), pack2(b0.z, b0.z), pack2(b0.w, b0.w),
                pack2(b1.x, b1.x), pack2(b1.y, b1.y), pack2(b1.z, b1.z), pack2(b1.w, b1.w)
            };
#pragma unroll
            for (int p = 0; p < 2; p++)
#pragma unroll
                for (int v = 0; v < 8; v++)
                    acc2[p][v] = ffma2(A2r[p], B2[v], acc2[p][v]);
        }

        if (t + 1 < T) {
            storeTile(buf ^ 1);
            __syncthreads();
            buf ^= 1;
        }
    }

    float bv8[8];
#pragma unroll
    for (int v = 0; v < 8; v++) bv8[v] = bias ? bias[n0 + tx * 8 + v] : 0.f;

#pragma unroll
    for (int p = 0; p < 2; p++) {
        float lo[8], hi[8];
#pragma unroll
        for (int v = 0; v < 8; v++) unpack2(acc2[p][v], lo[v], hi[v]);
#pragma unroll
        for (int half = 0; half < 2; half++) {
            float* src = half ? hi : lo;
            int m = m0 + ty * 4 + 2 * p + half;
            float o[8];
#pragma unroll
            for (int v = 0; v < 8; v++) {
                float val = src[v] + bv8[v];
                if (RELU) val = val > 0.f ? val : 0.f;
                o[v] = val;
            }
            *reinterpret_cast<float4*>(C + (size_t)m * N + n0 + tx * 8) =
                make_float4(o[0], o[1], o[2], o[3]);
            *reinterpret_cast<float4*>(C + (size_t)m * N + n0 + tx * 8 + 4) =
                make_float4(o[4], o[5], o[6], o[7]);
        }
    }
}

// Wrappers: device globals bound BY NAME (never passed from host).
__global__ __launch_bounds__(256, 3)
void sgemm1_kernel(const float* __restrict__ topo, const float* __restrict__ temp,
                   const float* __restrict__ Wg) {
    sgemm_body<0, 1>(topo, temp, Wg, nullptr, g_S, NODES, HID, KIN);
}
__global__ __launch_bounds__(256, 3)
void sgemm2_kernel() {
    sgemm_body<0, 0>(g_H, nullptr, g_WB, nullptr, g_PQ, NODES, 512, HID);
}

// ---------------------------------------------------------------------------
// Prefix-mean + bias + relu in H space:
// H[b,j,f] = relu( (1/j) * sum_{i<j} S[b,i,f] + b_gnn[f] )
// ---------------------------------------------------------------------------
__global__ void prefix_relu_kernel(const float* __restrict__ b_gnn) {
    int b = blockIdx.x;
    int f = threadIdx.x;
    float bias = b_gnn[f];
    float run = 0.f;
    const float* Sp = g_S + (size_t)b * NND * HID + f;
    float* Hp = g_H + (size_t)b * NND * HID + f;
#pragma unroll 8
    for (int j = 0; j < NND; j++) {
        float h = ((j == 0) ? 0.f : run / (float)j) + bias;
        Hp[j * HID] = h > 0.f ? h : 0.f;
        run += Sp[j * HID];
    }
}

// ---------------------------------------------------------------------------
// Weight head: warp per node, coalesced + shfl reduce.
// ---------------------------------------------------------------------------
__global__ void whead_kernel(const float* __restrict__ Ww) {
    int warp = (blockIdx.x * blockDim.x + threadIdx.x) >> 5;
    int lane = threadIdx.x & 31;
    if (warp >= NODES) return;
    const float* h = g_H + (size_t)warp * HID;
    float pw = 0.f, qw = 0.f;
#pragma unroll
    for (int t = 0; t < 8; t++) {
        int k = lane + 32 * t;
        float hv = h[k];
        pw = fmaf(hv, Ww[k], pw);
        qw = fmaf(hv, Ww[HID + k], qw);
    }
#pragma unroll
    for (int o = 16; o; o >>= 1) {
        pw += __shfl_xor_sync(0xFFFFFFFFu, pw, o);
        qw += __shfl_xor_sync(0xFFFFFFFFu, qw, o);
    }
    if (lane == 0) { g_pw[warp] = pw; g_qw[warp] = qw; }
}

// ---------------------------------------------------------------------------
// Edge kernel: CTA per graph, 1024 threads (32 warps), 128KB PQ slab in smem.
// ---------------------------------------------------------------------------
__global__ __launch_bounds__(1024, 1)
void edge_kernel(const float* __restrict__ gum,
                 const float* __restrict__ bm,
                 const float* __restrict__ bv,
                 const float* __restrict__ bw) {
    extern __shared__ float s_pq[];     // 64*512
    __shared__ float s_pw[NND], s_qw[NND], s_bm[OUTD], s_bv[OUTD];
    __shared__ int   s_eij[EPG];

    const int b = blockIdx.x;
    const int tid = threadIdx.x;

    const float4* src = reinterpret_cast<const float4*>(g_PQ + (size_t)b * NND * 512);
    float4* dst = reinterpret_cast<float4*>(s_pq);
    for (int i = tid; i < NND * 512 / 4; i += 1024) dst[i] = src[i];
    if (tid < NND)  { s_pw[tid] = g_pw[b * NND + tid]; s_qw[tid] = g_qw[b * NND + tid]; }
    if (tid < OUTD) { s_bm[tid] = bm[tid]; s_bv[tid] = bv[tid]; }
    for (int i = tid; i < EPG; i += 1024) s_eij[i] = g_eij[i];
    __syncthreads();

    const float bwv = bw[0];
    const int warp = tid >> 5, lane = tid & 31;
    double ssum = 0.0;

    for (int e = warp; e < EPG; e += 32) {
        int ij = s_eij[e];
        int i = ij >> 8, j = ij & 255;
        const float* P = s_pq + i * 512;
        const float* Q = s_pq + j * 512;
        float acc = 0.f;
#pragma unroll
        for (int t = 0; t < 4; t++) {
            int k = lane + 32 * t;
            float m   = P[k]       + Q[256 + k] + s_bm[k];
            float xv  = P[128 + k] + Q[384 + k] + s_bv[k];
            float sp  = fmaxf(xv, 0.f) + log1pf(expf(-fabsf(xv)));
            float var = sp + 1e-6f;
            acc += (m * m) / (var + 1e-8f);
        }
#pragma unroll
        for (int o = 16; o; o >>= 1) acc += __shfl_xor_sync(0xFFFFFFFFu, acc, o);

        if (lane == 0) {
            float sim = expf(-0.5f * (acc * (1.f / OUTD)));
            float wl  = s_pw[i] + s_qw[j] + bwv;
            float w   = 1.f / (1.f + expf(-wl));
            float u   = gum[b * EPG + e];
            float gb  = -logf(-logf(u));
            float z   = (w + gb) * 2.f;     // / TEMPERATURE (0.5)
            float s   = expf(z);
            g_prod[b * EPG + e] = sim * s;
            ssum += (double)s;
        }
    }
    if (lane == 0) atomicAdd(&g_sum, ssum);
}

__global__ void inv_kernel() { g_inv = (float)(1.0 / g_sum); }

__global__ void out_kernel(float* __restrict__ out) {
    int idx = blockIdx.x * 256 + threadIdx.x;
    int b = idx >> 12;
    int rem = idx & 4095;
    int i = rem >> 6, j = rem & 63;
    float val = 0.f;
    if (i < j) {
        int e = i * (NND - 1) - (i * (i - 1)) / 2 + (j - i - 1);
        val = g_prod[b * EPG + e] * g_inv;
    }
    out[idx] = val;
}

// ---------------------------------------------------------------------------
extern "C" void kernel_launch(void* const* d_in, const int* in_sizes, int n_in,
                              void* d_out, int out_size) {
    // Size-based binding. No __device__ global is ever passed as an arg.
    const float *x_topo = 0, *x_temp = 0, *gum = 0, *W_gnn = 0, *b_gnn = 0;
    const float *W_mean = 0, *b_mean = 0, *W_var = 0, *b_var = 0, *W_w = 0, *b_w = 0;
    for (int k = 0; k < n_in; k++) {
        const float* p = (const float*)d_in[k];
        switch (in_sizes[k]) {
            case 524288:  x_topo = p; break;
            case 2097152: x_temp = p; break;
            case 258048:  gum = p; break;
            case 81920:   W_gnn = p; break;
            case 256:     b_gnn = p; break;
            case 65536:   if (!W_mean) W_mean = p; else W_var = p; break;
            case 128:     if (!b_mean) b_mean = p; else b_var = p; break;
            case 512:     W_w = p; break;
            case 1:       b_w = p; break;
            default: break;
        }
    }
    float* out = (float*)d_out;

    cudaFuncSetAttribute(edge_kernel, cudaFuncAttributeMaxDynamicSharedMemorySize, 131072);

    setup_kernel<<<512, 256>>>(W_mean, W_var);

    // S = [topo|temp] @ W_gnn    [8192,256], K=320 (concat loader)
    { dim3 g(HID / 128, NODES / 64); sgemm1_kernel<<<g, 256>>>(x_topo, x_temp, W_gnn); }

    // H = relu(prefix-mean(S) + b)
    prefix_relu_kernel<<<BGR, HID>>>(b_gnn);

    // PQ = H @ WB                [8192,512], K=256
    { dim3 g(512 / 128, NODES / 64); sgemm2_kernel<<<g, 256>>>(); }

    whead_kernel<<<NODES / 8, 256>>>(W_w);

    edge_kernel<<<BGR, 1024, 131072>>>(gum, b_mean, b_var, b_w);

    inv_kernel<<<1, 1>>>();

    out_kernel<<<(BGR * NND * NND) / 256, 256>>>(out);
}

// round 12
// speedup vs baseline: 2.8203x; 1.1972x over previous
#include <cuda_runtime.h>
#include <math.h>

#define BGR   128
#define NND   64
#define KIN   320
#define HID   256
#define OUTD  128
#define EPG   2016
#define TOTE  (BGR*EPG)     // 258048
#define NODES (BGR*NND)     // 8192

// ---- scratch (device globals; referenced ONLY by name inside device code) ----
__device__ float  g_S[NODES*HID];     // X @ W_gnn, K-half 0
__device__ float  g_Sb[NODES*HID];    // X @ W_gnn, K-half 1
__device__ float  g_H[NODES*HID];
__device__ float  g_WB[HID*512];
__device__ float  g_PQ[NODES*512];
__device__ float  g_pw[NODES];
__device__ float  g_qw[NODES];
__device__ float  g_prod[TOTE];
__device__ double g_sum;
__device__ float  g_inv;
__device__ int    g_eij[EPG];

// ---------------------------------------------------------------------------
// f32x2 helpers
// ---------------------------------------------------------------------------
__device__ __forceinline__ unsigned long long pack2(float lo, float hi) {
    unsigned long long r;
    asm("mov.b64 %0, {%1, %2};" : "=l"(r) : "f"(lo), "f"(hi));
    return r;
}
__device__ __forceinline__ unsigned long long ffma2(unsigned long long a,
                                                    unsigned long long b,
                                                    unsigned long long c) {
    unsigned long long d;
    asm("fma.rn.f32x2 %0, %1, %2, %3;" : "=l"(d) : "l"(a), "l"(b), "l"(c));
    return d;
}
__device__ __forceinline__ void unpack2(unsigned long long v, float& lo, float& hi) {
    asm("mov.b64 {%0, %1}, %2;" : "=f"(lo), "=f"(hi) : "l"(v));
}

// ---------------------------------------------------------------------------
// Setup: zero sum, edge table, pack WB.
// ---------------------------------------------------------------------------
__global__ void setup_kernel(const float* __restrict__ Wm, const float* __restrict__ Wv) {
    int tid = blockIdx.x * blockDim.x + threadIdx.x;   // 131072 threads
    if (tid == 0) g_sum = 0.0;
    if (tid < EPG) {
        int e = tid, i = 0;
        while (e >= (NND - 1 - i)) { e -= (NND - 1 - i); i++; }
        g_eij[tid] = (i << 8) | (i + 1 + e);
    }
    int k = tid >> 9;
    int c = tid & 511;
    float v;
    if      (c < 128) v = Wm[k * 128 + c];
    else if (c < 256) v = Wv[k * 128 + (c - 128)];
    else if (c < 384) v = Wm[(256 + k) * 128 + (c - 256)];
    else              v = Wv[(256 + k) * 128 + (c - 384)];
    g_WB[tid] = v;
}

// ---------------------------------------------------------------------------
// Double-buffered tiled SGEMM (f32x2), R10 geometry: BM=BN=128, BK=16,
// 256 threads, 8x8 per thread. K range [kbeg, kbeg+16*T).
// CONCAT=1: A = virtual [topo(64) | temp(256)] with lda implicit.
// ---------------------------------------------------------------------------
template <int RELU, int CONCAT>
__device__ __forceinline__
void sgemm_body(const float* __restrict__ A, const float* __restrict__ A2,
                const float* __restrict__ B,
                const float* __restrict__ bias, float* __restrict__ C,
                int N, int lda, int kbeg, int T) {
    __shared__ float As[2][16][128];
    __shared__ float Bs[2][16][128];
    const int tid = threadIdx.x;
    const int m0 = blockIdx.y * 128;
    const int n0 = blockIdx.x * 128;
    const int tx = tid & 15;
    const int ty = tid >> 4;

    const int aRow0 = (tid)       >> 2, aC40 = ((tid)       & 3) * 4;
    const int aRow1 = (tid + 256) >> 2, aC41 = ((tid + 256) & 3) * 4;
    const int bRow0 = (tid)       >> 5, bC40 = ((tid)       & 31) * 4;
    const int bRow1 = (tid + 256) >> 5, bC41 = ((tid + 256) & 31) * 4;

    float4 pa0, pa1, pb0, pb1;

    auto loadA = [&](int grow, int kk) -> float4 {
        if (CONCAT) {
            if (kk < 64)
                return *reinterpret_cast<const float4*>(A  + (size_t)grow * 64  + kk);
            else
                return *reinterpret_cast<const float4*>(A2 + (size_t)grow * 256 + (kk - 64));
        }
        return *reinterpret_cast<const float4*>(A + (size_t)grow * lda + kk);
    };
    auto loadTile = [&](int k0) {
        pa0 = loadA(m0 + aRow0, k0 + aC40);
        pa1 = loadA(m0 + aRow1, k0 + aC41);
        pb0 = *reinterpret_cast<const float4*>(B + (size_t)(k0 + bRow0) * N + n0 + bC40);
        pb1 = *reinterpret_cast<const float4*>(B + (size_t)(k0 + bRow1) * N + n0 + bC41);
    };
    auto storeTile = [&](int buf) {
        As[buf][aC40 + 0][aRow0] = pa0.x;
        As[buf][aC40 + 1][aRow0] = pa0.y;
        As[buf][aC40 + 2][aRow0] = pa0.z;
        As[buf][aC40 + 3][aRow0] = pa0.w;
        As[buf][aC41 + 0][aRow1] = pa1.x;
        As[buf][aC41 + 1][aRow1] = pa1.y;
        As[buf][aC41 + 2][aRow1] = pa1.z;
        As[buf][aC41 + 3][aRow1] = pa1.w;
        *reinterpret_cast<float4*>(&Bs[buf][bRow0][bC40]) = pb0;
        *reinterpret_cast<float4*>(&Bs[buf][bRow1][bC41]) = pb1;
    };

    unsigned long long acc2[4][8];
#pragma unroll
    for (int p = 0; p < 4; p++)
#pragma unroll
        for (int v = 0; v < 8; v++) acc2[p][v] = 0ull;

    int buf = 0;
    loadTile(kbeg);
    storeTile(0);
    __syncthreads();

    for (int t = 0; t < T; t++) {
        if (t + 1 < T) loadTile(kbeg + (t + 1) * 16);

#pragma unroll
        for (int k = 0; k < 16; k++) {
            const unsigned long long* ap =
                reinterpret_cast<const unsigned long long*>(&As[buf][k][ty * 8]);
            unsigned long long A2r[4] = {ap[0], ap[1], ap[2], ap[3]};
            float4 b0 = *reinterpret_cast<const float4*>(&Bs[buf][k][tx * 8]);
            float4 b1 = *reinterpret_cast<const float4*>(&Bs[buf][k][tx * 8 + 4]);
            unsigned long long B2[8] = {
                pack2(b0.x, b0.x), pack2(b0.y, b0.y), pack2(b0.z, b0.z), pack2(b0.w, b0.w),
                pack2(b1.x, b1.x), pack2(b1.y, b1.y), pack2(b1.z, b1.z), pack2(b1.w, b1.w)
            };
#pragma unroll
            for (int p = 0; p < 4; p++)
#pragma unroll
                for (int v = 0; v < 8; v++)
                    acc2[p][v] = ffma2(A2r[p], B2[v], acc2[p][v]);
        }

        if (t + 1 < T) {
            storeTile(buf ^ 1);
            __syncthreads();
            buf ^= 1;
        }
    }

    float bv8[8];
#pragma unroll
    for (int v = 0; v < 8; v++) bv8[v] = bias ? bias[n0 + tx * 8 + v] : 0.f;

#pragma unroll
    for (int p = 0; p < 4; p++) {
        float lo[8], hi[8];
#pragma unroll
        for (int v = 0; v < 8; v++) unpack2(acc2[p][v], lo[v], hi[v]);
#pragma unroll
        for (int half = 0; half < 2; half++) {
            float* src = half ? hi : lo;
            int m = m0 + ty * 8 + 2 * p + half;
            float o[8];
#pragma unroll
            for (int v = 0; v < 8; v++) {
                float val = src[v] + bv8[v];
                if (RELU) val = val > 0.f ? val : 0.f;
                o[v] = val;
            }
            *reinterpret_cast<float4*>(C + (size_t)m * N + n0 + tx * 8) =
                make_float4(o[0], o[1], o[2], o[3]);
            *reinterpret_cast<float4*>(C + (size_t)m * N + n0 + tx * 8 + 4) =
                make_float4(o[4], o[5], o[6], o[7]);
        }
    }
}

// Wrappers (device globals bound BY NAME; split-K half chosen via blockIdx.z)
__global__ __launch_bounds__(256, 2)
void sgemm1_kernel(const float* __restrict__ topo, const float* __restrict__ temp,
                   const float* __restrict__ Wg) {
    float* C = blockIdx.z ? g_Sb : g_S;
    int kbeg = blockIdx.z ? 160 : 0;
    sgemm_body<0, 1>(topo, temp, Wg, nullptr, C, HID, KIN, kbeg, 10);
}
__global__ __launch_bounds__(256, 2)
void sgemm2_kernel() {
    sgemm_body<0, 0>(g_H, nullptr, g_WB, nullptr, g_PQ, 512, HID, 0, HID / 16);
}

// ---------------------------------------------------------------------------
// Prefix-mean + bias + relu (sums the two split-K halves deterministically):
// H[b,j,f] = relu( (1/j) * sum_{i<j} (S[b,i,f]+Sb[b,i,f]) + b_gnn[f] )
// ---------------------------------------------------------------------------
__global__ void prefix_relu_kernel(const float* __restrict__ b_gnn) {
    int b = blockIdx.x;
    int f = threadIdx.x;
    float bias = b_gnn[f];
    float run = 0.f;
    const float* Sp  = g_S  + (size_t)b * NND * HID + f;
    const float* Sbp = g_Sb + (size_t)b * NND * HID + f;
    float* Hp = g_H + (size_t)b * NND * HID + f;
#pragma unroll 8
    for (int j = 0; j < NND; j++) {
        float h = ((j == 0) ? 0.f : run / (float)j) + bias;
        Hp[j * HID] = h > 0.f ? h : 0.f;
        run += Sp[j * HID] + Sbp[j * HID];
    }
}

// ---------------------------------------------------------------------------
// Weight head: warp per node, coalesced + shfl reduce.
// ---------------------------------------------------------------------------
__global__ void whead_kernel(const float* __restrict__ Ww) {
    int warp = (blockIdx.x * blockDim.x + threadIdx.x) >> 5;
    int lane = threadIdx.x & 31;
    if (warp >= NODES) return;
    const float* h = g_H + (size_t)warp * HID;
    float pw = 0.f, qw = 0.f;
#pragma unroll
    for (int t = 0; t < 8; t++) {
        int k = lane + 32 * t;
        float hv = h[k];
        pw = fmaf(hv, Ww[k], pw);
        qw = fmaf(hv, Ww[HID + k], qw);
    }
#pragma unroll
    for (int o = 16; o; o >>= 1) {
        pw += __shfl_xor_sync(0xFFFFFFFFu, pw, o);
        qw += __shfl_xor_sync(0xFFFFFFFFu, qw, o);
    }
    if (lane == 0) { g_pw[warp] = pw; g_qw[warp] = qw; }
}

// ---------------------------------------------------------------------------
// Edge kernel: CTA per graph, 1024 threads, 128KB PQ slab in smem.
// ---------------------------------------------------------------------------
__global__ __launch_bounds__(1024, 1)
void edge_kernel(const float* __restrict__ gum,
                 const float* __restrict__ bm,
                 const float* __restrict__ bv,
                 const float* __restrict__ bw) {
    extern __shared__ float s_pq[];     // 64*512
    __shared__ float s_pw[NND], s_qw[NND], s_bm[OUTD], s_bv[OUTD];
    __shared__ int   s_eij[EPG];

    const int b = blockIdx.x;
    const int tid = threadIdx.x;

    const float4* src = reinterpret_cast<const float4*>(g_PQ + (size_t)b * NND * 512);
    float4* dst = reinterpret_cast<float4*>(s_pq);
    for (int i = tid; i < NND * 512 / 4; i += 1024) dst[i] = src[i];
    if (tid < NND)  { s_pw[tid] = g_pw[b * NND + tid]; s_qw[tid] = g_qw[b * NND + tid]; }
    if (tid < OUTD) { s_bm[tid] = bm[tid]; s_bv[tid] = bv[tid]; }
    for (int i = tid; i < EPG; i += 1024) s_eij[i] = g_eij[i];
    __syncthreads();

    const float bwv = bw[0];
    const int warp = tid >> 5, lane = tid & 31;
    double ssum = 0.0;

    for (int e = warp; e < EPG; e += 32) {
        int ij = s_eij[e];
        int i = ij >> 8, j = ij & 255;
        const float* P = s_pq + i * 512;
        const float* Q = s_pq + j * 512;
        float acc = 0.f;
#pragma unroll
        for (int t = 0; t < 4; t++) {
            int k = lane + 32 * t;
            float m   = P[k]       + Q[256 + k] + s_bm[k];
            float xv  = P[128 + k] + Q[384 + k] + s_bv[k];
            float sp  = fmaxf(xv, 0.f) + log1pf(expf(-fabsf(xv)));
            float var = sp + 1e-6f;
            acc += (m * m) / (var + 1e-8f);
        }
#pragma unroll
        for (int o = 16; o; o >>= 1) acc += __shfl_xor_sync(0xFFFFFFFFu, acc, o);

        if (lane == 0) {
            float sim = expf(-0.5f * (acc * (1.f / OUTD)));
            float wl  = s_pw[i] + s_qw[j] + bwv;
            float w   = 1.f / (1.f + expf(-wl));
            float u   = gum[b * EPG + e];
            float gb  = -logf(-logf(u));
            float z   = (w + gb) * 2.f;     // / TEMPERATURE (0.5)
            float s   = expf(z);
            g_prod[b * EPG + e] = sim * s;
            ssum += (double)s;
        }
    }
    if (lane == 0) atomicAdd(&g_sum, ssum);
}

__global__ void inv_kernel() { g_inv = (float)(1.0 / g_sum); }

__global__ void out_kernel(float* __restrict__ out) {
    int idx = blockIdx.x * 256 + threadIdx.x;
    int b = idx >> 12;
    int rem = idx & 4095;
    int i = rem >> 6, j = rem & 63;
    float val = 0.f;
    if (i < j) {
        int e = i * (NND - 1) - (i * (i - 1)) / 2 + (j - i - 1);
        val = g_prod[b * EPG + e] * g_inv;
    }
    out[idx] = val;
}

// ---------------------------------------------------------------------------
extern "C" void kernel_launch(void* const* d_in, const int* in_sizes, int n_in,
                              void* d_out, int out_size) {
    // Size-based binding. No __device__ global is ever passed as an arg.
    const float *x_topo = 0, *x_temp = 0, *gum = 0, *W_gnn = 0, *b_gnn = 0;
    const float *W_mean = 0, *b_mean = 0, *W_var = 0, *b_var = 0, *W_w = 0, *b_w = 0;
    for (int k = 0; k < n_in; k++) {
        const float* p = (const float*)d_in[k];
        switch (in_sizes[k]) {
            case 524288:  x_topo = p; break;
            case 2097152: x_temp = p; break;
            case 258048:  gum = p; break;
            case 81920:   W_gnn = p; break;
            case 256:     b_gnn = p; break;
            case 65536:   if (!W_mean) W_mean = p; else W_var = p; break;
            case 128:     if (!b_mean) b_mean = p; else b_var = p; break;
            case 512:     W_w = p; break;
            case 1:       b_w = p; break;
            default: break;
        }
    }
    float* out = (float*)d_out;

    cudaFuncSetAttribute(edge_kernel, cudaFuncAttributeMaxDynamicSharedMemorySize, 131072);

    setup_kernel<<<512, 256>>>(W_mean, W_var);

    // S halves = [topo|temp] @ W_gnn   (split-K x2: 256 CTAs)
    { dim3 g(HID / 128, NODES / 128, 2); sgemm1_kernel<<<g, 256>>>(x_topo, x_temp, W_gnn); }

    // H = relu(prefix-mean(S + Sb) + b)
    prefix_relu_kernel<<<BGR, HID>>>(b_gnn);

    // PQ = H @ WB   (256 CTAs)
    { dim3 g(512 / 128, NODES / 128); sgemm2_kernel<<<g, 256>>>(); }

    whead_kernel<<<NODES / 8, 256>>>(W_w);

    edge_kernel<<<BGR, 1024, 131072>>>(gum, b_mean, b_var, b_w);

    inv_kernel<<<1, 1>>>();

    out_kernel<<<(BGR * NND * NND) / 256, 256>>>(out);
}

// round 13
// speedup vs baseline: 3.2730x; 1.1605x over previous
#include <cuda_runtime.h>
#include <math.h>

#define BGR   128
#define NND   64
#define KIN   320
#define HID   256
#define OUTD  128
#define EPG   2016
#define TOTE  (BGR*EPG)     // 258048
#define NODES (BGR*NND)     // 8192

// ---- scratch (device globals; referenced ONLY by name inside device code) ----
__device__ float  g_S[NODES*HID];     // X @ W_gnn, K-half 0
__device__ float  g_Sb[NODES*HID];    // X @ W_gnn, K-half 1
__device__ float  g_H[NODES*HID];
__device__ float  g_WB[HID*512];
__device__ float  g_PQ[NODES*512];
__device__ float  g_pw[NODES];
__device__ float  g_qw[NODES];
__device__ float  g_prod[TOTE];
__device__ double g_sum;
__device__ float  g_inv;
__device__ int    g_eij[EPG];

// ---------------------------------------------------------------------------
// f32x2 helpers
// ---------------------------------------------------------------------------
__device__ __forceinline__ unsigned long long pack2(float lo, float hi) {
    unsigned long long r;
    asm("mov.b64 %0, {%1, %2};" : "=l"(r) : "f"(lo), "f"(hi));
    return r;
}
__device__ __forceinline__ unsigned long long ffma2(unsigned long long a,
                                                    unsigned long long b,
                                                    unsigned long long c) {
    unsigned long long d;
    asm("fma.rn.f32x2 %0, %1, %2, %3;" : "=l"(d) : "l"(a), "l"(b), "l"(c));
    return d;
}
__device__ __forceinline__ void unpack2(unsigned long long v, float& lo, float& hi) {
    asm("mov.b64 {%0, %1}, %2;" : "=f"(lo), "=f"(hi) : "l"(v));
}

// ---------------------------------------------------------------------------
// Setup: zero sum, edge table, pack WB.
// ---------------------------------------------------------------------------
__global__ void setup_kernel(const float* __restrict__ Wm, const float* __restrict__ Wv) {
    int tid = blockIdx.x * blockDim.x + threadIdx.x;   // 131072 threads
    if (tid == 0) g_sum = 0.0;
    if (tid < EPG) {
        int e = tid, i = 0;
        while (e >= (NND - 1 - i)) { e -= (NND - 1 - i); i++; }
        g_eij[tid] = (i << 8) | (i + 1 + e);
    }
    int k = tid >> 9;
    int c = tid & 511;
    float v;
    if      (c < 128) v = Wm[k * 128 + c];
    else if (c < 256) v = Wv[k * 128 + (c - 128)];
    else if (c < 384) v = Wm[(256 + k) * 128 + (c - 256)];
    else              v = Wv[(256 + k) * 128 + (c - 384)];
    g_WB[tid] = v;
}

// ---------------------------------------------------------------------------
// Double-buffered tiled SGEMM (f32x2): BM=BN=128, BK=16, 256 thr, 8x8/thread.
// K range [kbeg, kbeg+16*T). CONCAT=1: A = virtual [topo(64)|temp(256)].
// ---------------------------------------------------------------------------
template <int CONCAT>
__device__ __forceinline__
void sgemm_body(const float* __restrict__ A, const float* __restrict__ A2,
                const float* __restrict__ B, float* __restrict__ C,
                int N, int lda, int kbeg, int T) {
    __shared__ float As[2][16][128];
    __shared__ float Bs[2][16][128];
    const int tid = threadIdx.x;
    const int m0 = blockIdx.y * 128;
    const int n0 = blockIdx.x * 128;
    const int tx = tid & 15;
    const int ty = tid >> 4;

    const int aRow0 = (tid)       >> 2, aC40 = ((tid)       & 3) * 4;
    const int aRow1 = (tid + 256) >> 2, aC41 = ((tid + 256) & 3) * 4;
    const int bRow0 = (tid)       >> 5, bC40 = ((tid)       & 31) * 4;
    const int bRow1 = (tid + 256) >> 5, bC41 = ((tid + 256) & 31) * 4;

    float4 pa0, pa1, pb0, pb1;

    auto loadA = [&](int grow, int kk) -> float4 {
        if (CONCAT) {
            if (kk < 64)
                return *reinterpret_cast<const float4*>(A  + (size_t)grow * 64  + kk);
            else
                return *reinterpret_cast<const float4*>(A2 + (size_t)grow * 256 + (kk - 64));
        }
        return *reinterpret_cast<const float4*>(A + (size_t)grow * lda + kk);
    };
    auto loadTile = [&](int k0) {
        pa0 = loadA(m0 + aRow0, k0 + aC40);
        pa1 = loadA(m0 + aRow1, k0 + aC41);
        pb0 = *reinterpret_cast<const float4*>(B + (size_t)(k0 + bRow0) * N + n0 + bC40);
        pb1 = *reinterpret_cast<const float4*>(B + (size_t)(k0 + bRow1) * N + n0 + bC41);
    };
    auto storeTile = [&](int buf) {
        As[buf][aC40 + 0][aRow0] = pa0.x;
        As[buf][aC40 + 1][aRow0] = pa0.y;
        As[buf][aC40 + 2][aRow0] = pa0.z;
        As[buf][aC40 + 3][aRow0] = pa0.w;
        As[buf][aC41 + 0][aRow1] = pa1.x;
        As[buf][aC41 + 1][aRow1] = pa1.y;
        As[buf][aC41 + 2][aRow1] = pa1.z;
        As[buf][aC41 + 3][aRow1] = pa1.w;
        *reinterpret_cast<float4*>(&Bs[buf][bRow0][bC40]) = pb0;
        *reinterpret_cast<float4*>(&Bs[buf][bRow1][bC41]) = pb1;
    };

    unsigned long long acc2[4][8];
#pragma unroll
    for (int p = 0; p < 4; p++)
#pragma unroll
        for (int v = 0; v < 8; v++) acc2[p][v] = 0ull;

    int buf = 0;
    loadTile(kbeg);
    storeTile(0);
    __syncthreads();

    for (int t = 0; t < T; t++) {
        if (t + 1 < T) loadTile(kbeg + (t + 1) * 16);

#pragma unroll
        for (int k = 0; k < 16; k++) {
            const unsigned long long* ap =
                reinterpret_cast<const unsigned long long*>(&As[buf][k][ty * 8]);
            unsigned long long A2r[4] = {ap[0], ap[1], ap[2], ap[3]};
            float4 b0 = *reinterpret_cast<const float4*>(&Bs[buf][k][tx * 8]);
            float4 b1 = *reinterpret_cast<const float4*>(&Bs[buf][k][tx * 8 + 4]);
            unsigned long long B2[8] = {
                pack2(b0.x, b0.x), pack2(b0.y, b0.y), pack2(b0.z, b0.z), pack2(b0.w, b0.w),
                pack2(b1.x, b1.x), pack2(b1.y, b1.y), pack2(b1.z, b1.z), pack2(b1.w, b1.w)
            };
#pragma unroll
            for (int p = 0; p < 4; p++)
#pragma unroll
                for (int v = 0; v < 8; v++)
                    acc2[p][v] = ffma2(A2r[p], B2[v], acc2[p][v]);
        }

        if (t + 1 < T) {
            storeTile(buf ^ 1);
            __syncthreads();
            buf ^= 1;
        }
    }

#pragma unroll
    for (int p = 0; p < 4; p++) {
        float lo[8], hi[8];
#pragma unroll
        for (int v = 0; v < 8; v++) unpack2(acc2[p][v], lo[v], hi[v]);
#pragma unroll
        for (int half = 0; half < 2; half++) {
            float* src = half ? hi : lo;
            int m = m0 + ty * 8 + 2 * p + half;
            *reinterpret_cast<float4*>(C + (size_t)m * N + n0 + tx * 8) =
                make_float4(src[0], src[1], src[2], src[3]);
            *reinterpret_cast<float4*>(C + (size_t)m * N + n0 + tx * 8 + 4) =
                make_float4(src[4], src[5], src[6], src[7]);
        }
    }
}

__global__ __launch_bounds__(256, 2)
void sgemm1_kernel(const float* __restrict__ topo, const float* __restrict__ temp,
                   const float* __restrict__ Wg) {
    float* C = blockIdx.z ? g_Sb : g_S;
    int kbeg = blockIdx.z ? 160 : 0;
    sgemm_body<1>(topo, temp, Wg, C, HID, KIN, kbeg, 10);
}
__global__ __launch_bounds__(256, 2)
void sgemm2_kernel() {
    sgemm_body<0>(g_H, nullptr, g_WB, g_PQ, 512, HID, 0, HID / 16);
}

// ---------------------------------------------------------------------------
// Prefix-mean + bias + relu, with fused weight head.
// Phase 1 (per thread f): H[b,j,f] = relu(prefix_mean + bias); also stash in smem.
// Phase 2: warp-per-node dot products pw/qw from the smem H tile.
// Dynamic smem: 64*256 floats = 64KB.
// ---------------------------------------------------------------------------
__global__ void prefix_relu_kernel(const float* __restrict__ b_gnn,
                                   const float* __restrict__ Ww) {
    extern __shared__ float sh[];           // [64][256]
    int b = blockIdx.x;
    int f = threadIdx.x;
    float bias = b_gnn[f];
    float run = 0.f;
    const float* Sp  = g_S  + (size_t)b * NND * HID + f;
    const float* Sbp = g_Sb + (size_t)b * NND * HID + f;
    float* Hp = g_H + (size_t)b * NND * HID + f;
#pragma unroll 8
    for (int j = 0; j < NND; j++) {
        float h = ((j == 0) ? 0.f : run / (float)j) + bias;
        h = h > 0.f ? h : 0.f;
        Hp[j * HID] = h;
        sh[j * HID + f] = h;
        run += Sp[j * HID] + Sbp[j * HID];
    }
    __syncthreads();

    // whead: 8 warps x 8 nodes each
    int warp = f >> 5, lane = f & 31;
#pragma unroll
    for (int t = 0; t < 8; t++) {
        int j = warp * 8 + t;
        const float* h = sh + j * HID;
        float pw = 0.f, qw = 0.f;
#pragma unroll
        for (int q = 0; q < 8; q++) {
            int k = lane + 32 * q;
            float hv = h[k];
            pw = fmaf(hv, Ww[k], pw);
            qw = fmaf(hv, Ww[HID + k], qw);
        }
#pragma unroll
        for (int o = 16; o; o >>= 1) {
            pw += __shfl_xor_sync(0xFFFFFFFFu, pw, o);
            qw += __shfl_xor_sync(0xFFFFFFFFu, qw, o);
        }
        if (lane == 0) { g_pw[b * NND + j] = pw; g_qw[b * NND + j] = qw; }
    }
}

// ---------------------------------------------------------------------------
// Edge kernel: CTA per graph, 1024 threads, 128KB PQ slab in smem.
// Batched tails: reductions cooperative, transcendental tails parallel across lanes.
// ---------------------------------------------------------------------------
__global__ __launch_bounds__(1024, 1)
void edge_kernel(const float* __restrict__ gum,
                 const float* __restrict__ bm,
                 const float* __restrict__ bv,
                 const float* __restrict__ bw) {
    extern __shared__ float s_pq[];     // 64*512
    __shared__ float s_pw[NND], s_qw[NND], s_bm[OUTD], s_bv[OUTD];
    __shared__ int   s_eij[EPG];

    const int b = blockIdx.x;
    const int tid = threadIdx.x;

    const float4* src = reinterpret_cast<const float4*>(g_PQ + (size_t)b * NND * 512);
    float4* dst = reinterpret_cast<float4*>(s_pq);
    for (int i = tid; i < NND * 512 / 4; i += 1024) dst[i] = src[i];
    if (tid < NND)  { s_pw[tid] = g_pw[b * NND + tid]; s_qw[tid] = g_qw[b * NND + tid]; }
    if (tid < OUTD) { s_bm[tid] = bm[tid]; s_bv[tid] = bv[tid]; }
    for (int i = tid; i < EPG; i += 1024) s_eij[i] = g_eij[i];
    __syncthreads();

    const float bwv = bw[0];
    const int warp = tid >> 5, lane = tid & 31;
    double ssum = 0.0;

    // 63 edges per warp: e = warp + 32*g, g in [0,63)
    float accSave = 0.f;
    int myE = -1;
    for (int g = 0; g < 63; g++) {
        int e = warp + (g << 5);          // < 2016
        int ij = s_eij[e];
        int i = ij >> 8, j = ij & 255;
        const float* P = s_pq + i * 512;
        const float* Q = s_pq + j * 512;
        float acc = 0.f;
#pragma unroll
        for (int t = 0; t < 4; t++) {
            int k = lane + 32 * t;
            float m   = P[k]       + Q[256 + k] + s_bm[k];
            float xv  = P[128 + k] + Q[384 + k] + s_bv[k];
            float sp  = fmaxf(xv, 0.f) + log1pf(expf(-fabsf(xv)));
            float var = sp + 1e-6f;
            acc += (m * m) / (var + 1e-8f);
        }
#pragma unroll
        for (int o = 16; o; o >>= 1) acc += __shfl_xor_sync(0xFFFFFFFFu, acc, o);

        int slot = g & 31;
        if (lane == slot) { accSave = acc; myE = e; }

        if (slot == 31 || g == 62) {
            // parallel tails: each lane handles its saved edge
            if (myE >= 0) {
                int ij2 = s_eij[myE];
                int ii = ij2 >> 8, jj = ij2 & 255;
                float sim = expf(-0.5f * (accSave * (1.f / OUTD)));
                float wl  = s_pw[ii] + s_qw[jj] + bwv;
                float w   = 1.f / (1.f + expf(-wl));
                float u   = gum[b * EPG + myE];
                float gb  = -logf(-logf(u));
                float z   = (w + gb) * 2.f;     // / TEMPERATURE (0.5)
                float s   = expf(z);
                g_prod[b * EPG + myE] = sim * s;
                ssum += (double)s;
            }
            myE = -1;
        }
    }
    // ssum is spread across lanes now; reduce within warp (double via two shfls)
#pragma unroll
    for (int o = 16; o; o >>= 1) {
        double other = __shfl_xor_sync(0xFFFFFFFFu, ssum, o);
        ssum += other;
    }
    if (lane == 0) atomicAdd(&g_sum, ssum);
}

__global__ void inv_kernel() { g_inv = (float)(1.0 / g_sum); }

__global__ void out_kernel(float* __restrict__ out) {
    int idx = blockIdx.x * 256 + threadIdx.x;
    int b = idx >> 12;
    int rem = idx & 4095;
    int i = rem >> 6, j = rem & 63;
    float val = 0.f;
    if (i < j) {
        int e = i * (NND - 1) - (i * (i - 1)) / 2 + (j - i - 1);
        val = g_prod[b * EPG + e] * g_inv;
    }
    out[idx] = val;
}

// ---------------------------------------------------------------------------
extern "C" void kernel_launch(void* const* d_in, const int* in_sizes, int n_in,
                              void* d_out, int out_size) {
    // Size-based binding. No __device__ global is ever passed as an arg.
    const float *x_topo = 0, *x_temp = 0, *gum = 0, *W_gnn = 0, *b_gnn = 0;
    const float *W_mean = 0, *b_mean = 0, *W_var = 0, *b_var = 0, *W_w = 0, *b_w = 0;
    for (int k = 0; k < n_in; k++) {
        const float* p = (const float*)d_in[k];
        switch (in_sizes[k]) {
            case 524288:  x_topo = p; break;
            case 2097152: x_temp = p; break;
            case 258048:  gum = p; break;
            case 81920:   W_gnn = p; break;
            case 256:     b_gnn = p; break;
            case 65536:   if (!W_mean) W_mean = p; else W_var = p; break;
            case 128:     if (!b_mean) b_mean = p; else b_var = p; break;
            case 512:     W_w = p; break;
            case 1:       b_w = p; break;
            default: break;
        }
    }
    float* out = (float*)d_out;

    cudaFuncSetAttribute(edge_kernel, cudaFuncAttributeMaxDynamicSharedMemorySize, 131072);
    cudaFuncSetAttribute(prefix_relu_kernel, cudaFuncAttributeMaxDynamicSharedMemorySize, 65536);

    setup_kernel<<<512, 256>>>(W_mean, W_var);

    // S halves = [topo|temp] @ W_gnn   (split-K x2: 256 CTAs)
    { dim3 g(HID / 128, NODES / 128, 2); sgemm1_kernel<<<g, 256>>>(x_topo, x_temp, W_gnn); }

    // H = relu(prefix-mean(S + Sb) + b), fused whead
    prefix_relu_kernel<<<BGR, HID, 65536>>>(b_gnn, W_w);

    // PQ = H @ WB   (256 CTAs)
    { dim3 g(512 / 128, NODES / 128); sgemm2_kernel<<<g, 256>>>(); }

    edge_kernel<<<BGR, 1024, 131072>>>(gum, b_mean, b_var, b_w);

    inv_kernel<<<1, 1>>>();

    out_kernel<<<(BGR * NND * NND) / 256, 256>>>(out);
}

// round 14
// speedup vs baseline: 3.8902x; 1.1886x over previous
#include <cuda_runtime.h>
#include <math.h>

#define BGR   128
#define NND   64
#define KIN   320
#define HID   256
#define OUTD  128
#define EPG   2016
#define TOTE  (BGR*EPG)     // 258048
#define NODES (BGR*NND)     // 8192

// ---- scratch (device globals; referenced ONLY by name inside device code) ----
__device__ float  g_S[NODES*HID];     // X @ W_gnn, K-half 0
__device__ float  g_Sb[NODES*HID];    // X @ W_gnn, K-half 1
__device__ float  g_H[NODES*HID];
__device__ float  g_PQ[NODES*512];
__device__ float  g_pw[NODES];
__device__ float  g_qw[NODES];
__device__ float  g_prod[TOTE];
__device__ double g_sum;
__device__ float  g_inv;
__device__ int    g_eij[EPG];

// ---------------------------------------------------------------------------
// f32x2 helpers
// ---------------------------------------------------------------------------
__device__ __forceinline__ unsigned long long pack2(float lo, float hi) {
    unsigned long long r;
    asm("mov.b64 %0, {%1, %2};" : "=l"(r) : "f"(lo), "f"(hi));
    return r;
}
__device__ __forceinline__ unsigned long long ffma2(unsigned long long a,
                                                    unsigned long long b,
                                                    unsigned long long c) {
    unsigned long long d;
    asm("fma.rn.f32x2 %0, %1, %2, %3;" : "=l"(d) : "l"(a), "l"(b), "l"(c));
    return d;
}
__device__ __forceinline__ void unpack2(unsigned long long v, float& lo, float& hi) {
    asm("mov.b64 {%0, %1}, %2;" : "=f"(lo), "=f"(hi) : "l"(v));
}

// ---------------------------------------------------------------------------
// Setup: zero sum + edge table only (WB packing now fused into sgemm2 loads).
// ---------------------------------------------------------------------------
__global__ void setup_kernel() {
    int tid = blockIdx.x * blockDim.x + threadIdx.x;
    if (tid == 0) g_sum = 0.0;
    if (tid < EPG) {
        int e = tid, i = 0;
        while (e >= (NND - 1 - i)) { e -= (NND - 1 - i); i++; }
        g_eij[tid] = (i << 8) | (i + 1 + e);
    }
}

// ---------------------------------------------------------------------------
// Double-buffered tiled SGEMM (f32x2): BM=BN=128, BK=16, 256 thr, 8x8/thread.
// CONCAT=1: A = virtual [topo(64)|temp(256)].
// WB=1: B is the virtual packed [256,512] head-weight matrix, materialized
//       on the fly from Wm/Wv (passed as B/B2):
//       col<128 -> Wm[k,c]; <256 -> Wv[k,c-128]; <384 -> Wm[256+k,c-256];
//       else Wv[256+k,c-384].  Each float4 is wholly inside one 128-block.
// ---------------------------------------------------------------------------
template <int CONCAT, int WB>
__device__ __forceinline__
void sgemm_body(const float* __restrict__ A, const float* __restrict__ A2,
                const float* __restrict__ B, const float* __restrict__ B2,
                float* __restrict__ C,
                int N, int lda, int kbeg, int T) {
    __shared__ float As[2][16][128];
    __shared__ float Bs[2][16][128];
    const int tid = threadIdx.x;
    const int m0 = blockIdx.y * 128;
    const int n0 = blockIdx.x * 128;
    const int tx = tid & 15;
    const int ty = tid >> 4;

    const int aRow0 = (tid)       >> 2, aC40 = ((tid)       & 3) * 4;
    const int aRow1 = (tid + 256) >> 2, aC41 = ((tid + 256) & 3) * 4;
    const int bRow0 = (tid)       >> 5, bC40 = ((tid)       & 31) * 4;
    const int bRow1 = (tid + 256) >> 5, bC41 = ((tid + 256) & 31) * 4;

    float4 pa0, pa1, pb0, pb1;

    auto loadA = [&](int grow, int kk) -> float4 {
        if (CONCAT) {
            if (kk < 64)
                return *reinterpret_cast<const float4*>(A  + (size_t)grow * 64  + kk);
            else
                return *reinterpret_cast<const float4*>(A2 + (size_t)grow * 256 + (kk - 64));
        }
        return *reinterpret_cast<const float4*>(A + (size_t)grow * lda + kk);
    };
    auto loadB = [&](int k, int gc) -> float4 {
        if (WB) {
            int blk = gc >> 7;
            int c   = gc & 127;
            const float* W = (blk == 0 || blk == 2) ? B : B2;   // Wm : Wv
            int kk = (blk < 2) ? k : (256 + k);
            return *reinterpret_cast<const float4*>(W + (size_t)kk * 128 + c);
        }
        return *reinterpret_cast<const float4*>(B + (size_t)k * N + gc);
    };
    auto loadTile = [&](int k0) {
        pa0 = loadA(m0 + aRow0, k0 + aC40);
        pa1 = loadA(m0 + aRow1, k0 + aC41);
        pb0 = loadB(k0 + bRow0, n0 + bC40);
        pb1 = loadB(k0 + bRow1, n0 + bC41);
    };
    auto storeTile = [&](int buf) {
        As[buf][aC40 + 0][aRow0] = pa0.x;
        As[buf][aC40 + 1][aRow0] = pa0.y;
        As[buf][aC40 + 2][aRow0] = pa0.z;
        As[buf][aC40 + 3][aRow0] = pa0.w;
        As[buf][aC41 + 0][aRow1] = pa1.x;
        As[buf][aC41 + 1][aRow1] = pa1.y;
        As[buf][aC41 + 2][aRow1] = pa1.z;
        As[buf][aC41 + 3][aRow1] = pa1.w;
        *reinterpret_cast<float4*>(&Bs[buf][bRow0][bC40]) = pb0;
        *reinterpret_cast<float4*>(&Bs[buf][bRow1][bC41]) = pb1;
    };

    unsigned long long acc2[4][8];
#pragma unroll
    for (int p = 0; p < 4; p++)
#pragma unroll
        for (int v = 0; v < 8; v++) acc2[p][v] = 0ull;

    int buf = 0;
    loadTile(kbeg);
    storeTile(0);
    __syncthreads();

    for (int t = 0; t < T; t++) {
        if (t + 1 < T) loadTile(kbeg + (t + 1) * 16);

#pragma unroll
        for (int k = 0; k < 16; k++) {
            const unsigned long long* ap =
                reinterpret_cast<const unsigned long long*>(&As[buf][k][ty * 8]);
            unsigned long long A2r[4] = {ap[0], ap[1], ap[2], ap[3]};
            float4 b0 = *reinterpret_cast<const float4*>(&Bs[buf][k][tx * 8]);
            float4 b1 = *reinterpret_cast<const float4*>(&Bs[buf][k][tx * 8 + 4]);
            unsigned long long B2r[8] = {
                pack2(b0.x, b0.x), pack2(b0.y, b0.y), pack2(b0.z, b0.z), pack2(b0.w, b0.w),
                pack2(b1.x, b1.x), pack2(b1.y, b1.y), pack2(b1.z, b1.z), pack2(b1.w, b1.w)
            };
#pragma unroll
            for (int p = 0; p < 4; p++)
#pragma unroll
                for (int v = 0; v < 8; v++)
                    acc2[p][v] = ffma2(A2r[p], B2r[v], acc2[p][v]);
        }

        if (t + 1 < T) {
            storeTile(buf ^ 1);
            __syncthreads();
            buf ^= 1;
        }
    }

#pragma unroll
    for (int p = 0; p < 4; p++) {
        float lo[8], hi[8];
#pragma unroll
        for (int v = 0; v < 8; v++) unpack2(acc2[p][v], lo[v], hi[v]);
#pragma unroll
        for (int half = 0; half < 2; half++) {
            float* src = half ? hi : lo;
            int m = m0 + ty * 8 + 2 * p + half;
            *reinterpret_cast<float4*>(C + (size_t)m * N + n0 + tx * 8) =
                make_float4(src[0], src[1], src[2], src[3]);
            *reinterpret_cast<float4*>(C + (size_t)m * N + n0 + tx * 8 + 4) =
                make_float4(src[4], src[5], src[6], src[7]);
        }
    }
}

__global__ __launch_bounds__(256, 2)
void sgemm1_kernel(const float* __restrict__ topo, const float* __restrict__ temp,
                   const float* __restrict__ Wg) {
    float* C = blockIdx.z ? g_Sb : g_S;
    int kbeg = blockIdx.z ? 160 : 0;
    sgemm_body<1, 0>(topo, temp, Wg, nullptr, C, HID, KIN, kbeg, 10);
}
__global__ __launch_bounds__(256, 2)
void sgemm2_kernel(const float* __restrict__ Wm, const float* __restrict__ Wv) {
    sgemm_body<0, 1>(g_H, nullptr, Wm, Wv, g_PQ, 512, HID, 0, HID / 16);
}

// ---------------------------------------------------------------------------
// Prefix-mean + bias + relu, fused weight head. Dyn smem 64KB.
// ---------------------------------------------------------------------------
__global__ void prefix_relu_kernel(const float* __restrict__ b_gnn,
                                   const float* __restrict__ Ww) {
    extern __shared__ float sh[];           // [64][256]
    int b = blockIdx.x;
    int f = threadIdx.x;
    float bias = b_gnn[f];
    float run = 0.f;
    const float* Sp  = g_S  + (size_t)b * NND * HID + f;
    const float* Sbp = g_Sb + (size_t)b * NND * HID + f;
    float* Hp = g_H + (size_t)b * NND * HID + f;
#pragma unroll 8
    for (int j = 0; j < NND; j++) {
        float h = ((j == 0) ? 0.f : run / (float)j) + bias;
        h = h > 0.f ? h : 0.f;
        Hp[j * HID] = h;
        sh[j * HID + f] = h;
        run += Sp[j * HID] + Sbp[j * HID];
    }
    __syncthreads();

    int warp = f >> 5, lane = f & 31;
#pragma unroll
    for (int t = 0; t < 8; t++) {
        int j = warp * 8 + t;
        const float* h = sh + j * HID;
        float pw = 0.f, qw = 0.f;
#pragma unroll
        for (int q = 0; q < 8; q++) {
            int k = lane + 32 * q;
            float hv = h[k];
            pw = fmaf(hv, Ww[k], pw);
            qw = fmaf(hv, Ww[HID + k], qw);
        }
#pragma unroll
        for (int o = 16; o; o >>= 1) {
            pw += __shfl_xor_sync(0xFFFFFFFFu, pw, o);
            qw += __shfl_xor_sync(0xFFFFFFFFu, qw, o);
        }
        if (lane == 0) { g_pw[b * NND + j] = pw; g_qw[b * NND + j] = qw; }
    }
}

// ---------------------------------------------------------------------------
// Edge kernel: CTA per graph, 1024 threads, 128KB PQ slab in smem.
// 128-dim loop uses MUFU intrinsics (__expf/__logf/__fdividef) — var only
// needs ~1e-3 rel accuracy. Per-edge gumbel/softmax tail stays accurate.
// ---------------------------------------------------------------------------
__global__ __launch_bounds__(1024, 1)
void edge_kernel(const float* __restrict__ gum,
                 const float* __restrict__ bm,
                 const float* __restrict__ bv,
                 const float* __restrict__ bw) {
    extern __shared__ float s_pq[];     // 64*512
    __shared__ float s_pw[NND], s_qw[NND], s_bm[OUTD], s_bv[OUTD];
    __shared__ int   s_eij[EPG];

    const int b = blockIdx.x;
    const int tid = threadIdx.x;

    const float4* src = reinterpret_cast<const float4*>(g_PQ + (size_t)b * NND * 512);
    float4* dst = reinterpret_cast<float4*>(s_pq);
    for (int i = tid; i < NND * 512 / 4; i += 1024) dst[i] = src[i];
    if (tid < NND)  { s_pw[tid] = g_pw[b * NND + tid]; s_qw[tid] = g_qw[b * NND + tid]; }
    if (tid < OUTD) { s_bm[tid] = bm[tid]; s_bv[tid] = bv[tid]; }
    for (int i = tid; i < EPG; i += 1024) s_eij[i] = g_eij[i];
    __syncthreads();

    const float bwv = bw[0];
    const int warp = tid >> 5, lane = tid & 31;
    double ssum = 0.0;

    float accSave = 0.f;
    int myE = -1;
    for (int g = 0; g < 63; g++) {
        int e = warp + (g << 5);          // < 2016
        int ij = s_eij[e];
        int i = ij >> 8, j = ij & 255;
        const float* P = s_pq + i * 512;
        const float* Q = s_pq + j * 512;
        float acc = 0.f;
#pragma unroll
        for (int t = 0; t < 4; t++) {
            int k = lane + 32 * t;
            float m   = P[k]       + Q[256 + k] + s_bm[k];
            float xv  = P[128 + k] + Q[384 + k] + s_bv[k];
            float sp  = fmaxf(xv, 0.f) + __logf(1.f + __expf(-fabsf(xv)));
            float var = sp + 1e-6f;
            acc += __fdividef(m * m, var + 1e-8f);
        }
#pragma unroll
        for (int o = 16; o; o >>= 1) acc += __shfl_xor_sync(0xFFFFFFFFu, acc, o);

        int slot = g & 31;
        if (lane == slot) { accSave = acc; myE = e; }

        if (slot == 31 || g == 62) {
            if (myE >= 0) {
                int ij2 = s_eij[myE];
                int ii = ij2 >> 8, jj = ij2 & 255;
                float sim = expf(-0.5f * (accSave * (1.f / OUTD)));
                float wl  = s_pw[ii] + s_qw[jj] + bwv;
                float w   = 1.f / (1.f + expf(-wl));
                float u   = gum[b * EPG + myE];
                float gb  = -logf(-logf(u));
                float z   = (w + gb) * 2.f;     // / TEMPERATURE (0.5)
                float s   = expf(z);
                g_prod[b * EPG + myE] = sim * s;
                ssum += (double)s;
            }
            myE = -1;
        }
    }
#pragma unroll
    for (int o = 16; o; o >>= 1) {
        double other = __shfl_xor_sync(0xFFFFFFFFu, ssum, o);
        ssum += other;
    }
    if (lane == 0) atomicAdd(&g_sum, ssum);
}

__global__ void inv_kernel() { g_inv = (float)(1.0 / g_sum); }

__global__ void out_kernel(float* __restrict__ out) {
    int idx = blockIdx.x * 256 + threadIdx.x;
    int b = idx >> 12;
    int rem = idx & 4095;
    int i = rem >> 6, j = rem & 63;
    float val = 0.f;
    if (i < j) {
        int e = i * (NND - 1) - (i * (i - 1)) / 2 + (j - i - 1);
        val = g_prod[b * EPG + e] * g_inv;
    }
    out[idx] = val;
}

// ---------------------------------------------------------------------------
extern "C" void kernel_launch(void* const* d_in, const int* in_sizes, int n_in,
                              void* d_out, int out_size) {
    // Size-based binding. No __device__ global is ever passed as an arg.
    const float *x_topo = 0, *x_temp = 0, *gum = 0, *W_gnn = 0, *b_gnn = 0;
    const float *W_mean = 0, *b_mean = 0, *W_var = 0, *b_var = 0, *W_w = 0, *b_w = 0;
    for (int k = 0; k < n_in; k++) {
        const float* p = (const float*)d_in[k];
        switch (in_sizes[k]) {
            case 524288:  x_topo = p; break;
            case 2097152: x_temp = p; break;
            case 258048:  gum = p; break;
            case 81920:   W_gnn = p; break;
            case 256:     b_gnn = p; break;
            case 65536:   if (!W_mean) W_mean = p; else W_var = p; break;
            case 128:     if (!b_mean) b_mean = p; else b_var = p; break;
            case 512:     W_w = p; break;
            case 1:       b_w = p; break;
            default: break;
        }
    }
    float* out = (float*)d_out;

    cudaFuncSetAttribute(edge_kernel, cudaFuncAttributeMaxDynamicSharedMemorySize, 131072);
    cudaFuncSetAttribute(prefix_relu_kernel, cudaFuncAttributeMaxDynamicSharedMemorySize, 65536);

    setup_kernel<<<8, 256>>>();

    // S halves = [topo|temp] @ W_gnn   (split-K x2: 256 CTAs)
    { dim3 g(HID / 128, NODES / 128, 2); sgemm1_kernel<<<g, 256>>>(x_topo, x_temp, W_gnn); }

    // H = relu(prefix-mean(S + Sb) + b), fused whead
    prefix_relu_kernel<<<BGR, HID, 65536>>>(b_gnn, W_w);

    // PQ = H @ WB(virtual)   (256 CTAs; WB materialized from Wm/Wv in-loader)
    { dim3 g(512 / 128, NODES / 128); sgemm2_kernel<<<g, 256>>>(W_mean, W_var); }

    edge_kernel<<<BGR, 1024, 131072>>>(gum, b_mean, b_var, b_w);

    inv_kernel<<<1, 1>>>();

    out_kernel<<<(BGR * NND * NND) / 256, 256>>>(out);
}

// round 17
// speedup vs baseline: 4.9967x; 1.2844x over previous
#include <cuda_runtime.h>
#include <math.h>
#include <stdint.h>

#define BGR   128
#define NND   64
#define KIN   320
#define HID   256
#define OUTD  128
#define EPG   2016
#define TOTE  (BGR*EPG)     // 258048
#define NODES (BGR*NND)     // 8192

// ---- scratch (device globals; referenced ONLY by name inside device code) ----
__device__ float  g_S[NODES*HID];     // X @ W_gnn, K-half 0
__device__ float  g_Sb[NODES*HID];    // X @ W_gnn, K-half 1
__device__ float  g_H[NODES*HID];
__device__ float  g_PQ[NODES*512];
__device__ float  g_pw[NODES];
__device__ float  g_qw[NODES];
__device__ float  g_prod[TOTE];
__device__ double g_sum;
__device__ float  g_inv;
__device__ int    g_eij[EPG];

// ---------------------------------------------------------------------------
// f32x2 helpers (sgemm1)
// ---------------------------------------------------------------------------
__device__ __forceinline__ unsigned long long pack2(float lo, float hi) {
    unsigned long long r;
    asm("mov.b64 %0, {%1, %2};" : "=l"(r) : "f"(lo), "f"(hi));
    return r;
}
__device__ __forceinline__ unsigned long long ffma2(unsigned long long a,
                                                    unsigned long long b,
                                                    unsigned long long c) {
    unsigned long long d;
    asm("fma.rn.f32x2 %0, %1, %2, %3;" : "=l"(d) : "l"(a), "l"(b), "l"(c));
    return d;
}
__device__ __forceinline__ void unpack2(unsigned long long v, float& lo, float& hi) {
    asm("mov.b64 {%0, %1}, %2;" : "=f"(lo), "=f"(hi) : "l"(v));
}

// ---------------------------------------------------------------------------
// tf32 mma.sync helpers (baseline PTX, works on plain sm_103 target)
// ---------------------------------------------------------------------------
__device__ __forceinline__ uint32_t cvt_tf32(float v) {
    uint32_t r;
    asm("cvt.rna.tf32.f32 %0, %1;" : "=r"(r) : "f"(v));
    return r;
}
__device__ __forceinline__ void mma_tf32(float* c,
                                         uint32_t a0, uint32_t a1, uint32_t a2, uint32_t a3,
                                         uint32_t b0, uint32_t b1) {
    asm volatile(
        "mma.sync.aligned.m16n8k8.row.col.f32.tf32.tf32.f32 "
        "{%0,%1,%2,%3}, {%4,%5,%6,%7}, {%8,%9}, {%0,%1,%2,%3};"
        : "+f"(c[0]), "+f"(c[1]), "+f"(c[2]), "+f"(c[3])
        : "r"(a0), "r"(a1), "r"(a2), "r"(a3), "r"(b0), "r"(b1));
}

// ---------------------------------------------------------------------------
// Setup: zero sum + edge table.
// ---------------------------------------------------------------------------
__global__ void setup_kernel() {
    int tid = blockIdx.x * blockDim.x + threadIdx.x;
    if (tid == 0) g_sum = 0.0;
    if (tid < EPG) {
        int e = tid, i = 0;
        while (e >= (NND - 1 - i)) { e -= (NND - 1 - i); i++; }
        g_eij[tid] = (i << 8) | (i + 1 + e);
    }
}

// ---------------------------------------------------------------------------
// sgemm1: SIMT f32x2 (unchanged from R14). BM=BN=128, BK=16, split-K x2.
// ---------------------------------------------------------------------------
__device__ __forceinline__
void sgemm1_body(const float* __restrict__ A, const float* __restrict__ A2,
                 const float* __restrict__ B, float* __restrict__ C,
                 int N, int kbeg, int T) {
    __shared__ float As[2][16][128];
    __shared__ float Bs[2][16][128];
    const int tid = threadIdx.x;
    const int m0 = blockIdx.y * 128;
    const int n0 = blockIdx.x * 128;
    const int tx = tid & 15;
    const int ty = tid >> 4;

    const int aRow0 = (tid)       >> 2, aC40 = ((tid)       & 3) * 4;
    const int aRow1 = (tid + 256) >> 2, aC41 = ((tid + 256) & 3) * 4;
    const int bRow0 = (tid)       >> 5, bC40 = ((tid)       & 31) * 4;
    const int bRow1 = (tid + 256) >> 5, bC41 = ((tid + 256) & 31) * 4;

    float4 pa0, pa1, pb0, pb1;

    auto loadA = [&](int grow, int kk) -> float4 {
        if (kk < 64)
            return *reinterpret_cast<const float4*>(A  + (size_t)grow * 64  + kk);
        else
            return *reinterpret_cast<const float4*>(A2 + (size_t)grow * 256 + (kk - 64));
    };
    auto loadTile = [&](int k0) {
        pa0 = loadA(m0 + aRow0, k0 + aC40);
        pa1 = loadA(m0 + aRow1, k0 + aC41);
        pb0 = *reinterpret_cast<const float4*>(B + (size_t)(k0 + bRow0) * N + n0 + bC40);
        pb1 = *reinterpret_cast<const float4*>(B + (size_t)(k0 + bRow1) * N + n0 + bC41);
    };
    auto storeTile = [&](int buf) {
        As[buf][aC40 + 0][aRow0] = pa0.x;
        As[buf][aC40 + 1][aRow0] = pa0.y;
        As[buf][aC40 + 2][aRow0] = pa0.z;
        As[buf][aC40 + 3][aRow0] = pa0.w;
        As[buf][aC41 + 0][aRow1] = pa1.x;
        As[buf][aC41 + 1][aRow1] = pa1.y;
        As[buf][aC41 + 2][aRow1] = pa1.z;
        As[buf][aC41 + 3][aRow1] = pa1.w;
        *reinterpret_cast<float4*>(&Bs[buf][bRow0][bC40]) = pb0;
        *reinterpret_cast<float4*>(&Bs[buf][bRow1][bC41]) = pb1;
    };

    unsigned long long acc2[4][8];
#pragma unroll
    for (int p = 0; p < 4; p++)
#pragma unroll
        for (int v = 0; v < 8; v++) acc2[p][v] = 0ull;

    int buf = 0;
    loadTile(kbeg);
    storeTile(0);
    __syncthreads();

    for (int t = 0; t < T; t++) {
        if (t + 1 < T) loadTile(kbeg + (t + 1) * 16);
#pragma unroll
        for (int k = 0; k < 16; k++) {
            const unsigned long long* ap =
                reinterpret_cast<const unsigned long long*>(&As[buf][k][ty * 8]);
            unsigned long long A2r[4] = {ap[0], ap[1], ap[2], ap[3]};
            float4 b0 = *reinterpret_cast<const float4*>(&Bs[buf][k][tx * 8]);
            float4 b1 = *reinterpret_cast<const float4*>(&Bs[buf][k][tx * 8 + 4]);
            unsigned long long B2r[8] = {
                pack2(b0.x, b0.x), pack2(b0.y, b0.y), pack2(b0.z, b0.z), pack2(b0.w, b0.w),
                pack2(b1.x, b1.x), pack2(b1.y, b1.y), pack2(b1.z, b1.z), pack2(b1.w, b1.w)
            };
#pragma unroll
            for (int p = 0; p < 4; p++)
#pragma unroll
                for (int v = 0; v < 8; v++)
                    acc2[p][v] = ffma2(A2r[p], B2r[v], acc2[p][v]);
        }
        if (t + 1 < T) {
            storeTile(buf ^ 1);
            __syncthreads();
            buf ^= 1;
        }
    }

#pragma unroll
    for (int p = 0; p < 4; p++) {
        float lo[8], hi[8];
#pragma unroll
        for (int v = 0; v < 8; v++) unpack2(acc2[p][v], lo[v], hi[v]);
#pragma unroll
        for (int half = 0; half < 2; half++) {
            float* src = half ? hi : lo;
            int m = m0 + ty * 8 + 2 * p + half;
            *reinterpret_cast<float4*>(C + (size_t)m * N + n0 + tx * 8) =
                make_float4(src[0], src[1], src[2], src[3]);
            *reinterpret_cast<float4*>(C + (size_t)m * N + n0 + tx * 8 + 4) =
                make_float4(src[4], src[5], src[6], src[7]);
        }
    }
}

__global__ __launch_bounds__(256, 2)
void sgemm1_kernel(const float* __restrict__ topo, const float* __restrict__ temp,
                   const float* __restrict__ Wg) {
    float* C = blockIdx.z ? g_Sb : g_S;
    int kbeg = blockIdx.z ? 160 : 0;
    sgemm1_body(topo, temp, Wg, C, HID, kbeg, 10);
}

// ---------------------------------------------------------------------------
// sgemm2: mma.sync tf32. PQ[8192,512] = H @ WB(virtual from Wm/Wv).
// Grid (4, 64) = 256 CTAs; CTA 128x128, 8 warps, warp tile 32x64
// (2 m-tiles x 8 n-tiles of m16n8k8). BK=16 double-buffered, stride-136
// smem (conflict-free fragment loads: bank = 8*(lane%4)+lane/4).
// WB: col block = blockIdx.x (0..3): 0->Wm[k], 1->Wv[k], 2->Wm[256+k], 3->Wv[256+k].
// ---------------------------------------------------------------------------
__global__ __launch_bounds__(256, 2)
void sgemm2_mma_kernel(const float* __restrict__ Wm, const float* __restrict__ Wv) {
    __shared__ uint32_t As[2][16][136];   // [k][m], tf32 bits
    __shared__ uint32_t Bs[2][16][136];   // [k][n], tf32 bits

    const int tid = threadIdx.x;
    const int wid = tid >> 5;
    const int lane = tid & 31;
    const int m0 = blockIdx.y * 128;
    const int blk = blockIdx.x;           // n-block 0..3
    const int n0 = blk * 128;

    const float* W = (blk == 0 || blk == 2) ? Wm : Wv;
    const int krow0 = (blk < 2) ? 0 : 256;

    // staging coords (2 float4 per thread for each of A and B)
    const int aRow0 = (tid)       >> 2, aC40 = ((tid)       & 3) * 4;
    const int aRow1 = (tid + 256) >> 2, aC41 = ((tid + 256) & 3) * 4;
    const int bRow0 = (tid)       >> 5, bC40 = ((tid)       & 31) * 4;
    const int bRow1 = (tid + 256) >> 5, bC41 = ((tid + 256) & 31) * 4;

    uint4 pa0, pa1, pb0, pb1;

    auto cvt4 = [](float4 v) -> uint4 {
        uint4 t;
        t.x = cvt_tf32(v.x); t.y = cvt_tf32(v.y);
        t.z = cvt_tf32(v.z); t.w = cvt_tf32(v.w);
        return t;
    };
    auto loadTile = [&](int k0) {
        pa0 = cvt4(*reinterpret_cast<const float4*>(g_H + (size_t)(m0 + aRow0) * HID + k0 + aC40));
        pa1 = cvt4(*reinterpret_cast<const float4*>(g_H + (size_t)(m0 + aRow1) * HID + k0 + aC41));
        pb0 = cvt4(*reinterpret_cast<const float4*>(W + (size_t)(krow0 + k0 + bRow0) * 128 + bC40));
        pb1 = cvt4(*reinterpret_cast<const float4*>(W + (size_t)(krow0 + k0 + bRow1) * 128 + bC41));
    };
    auto storeTile = [&](int buf) {
        As[buf][aC40 + 0][aRow0] = pa0.x;
        As[buf][aC40 + 1][aRow0] = pa0.y;
        As[buf][aC40 + 2][aRow0] = pa0.z;
        As[buf][aC40 + 3][aRow0] = pa0.w;
        As[buf][aC41 + 0][aRow1] = pa1.x;
        As[buf][aC41 + 1][aRow1] = pa1.y;
        As[buf][aC41 + 2][aRow1] = pa1.z;
        As[buf][aC41 + 3][aRow1] = pa1.w;
        *reinterpret_cast<uint4*>(&Bs[buf][bRow0][bC40]) = pb0;
        *reinterpret_cast<uint4*>(&Bs[buf][bRow1][bC41]) = pb1;
    };

    const int warp_m = (wid & 3) * 32;
    const int warp_n = (wid >> 2) * 64;
    const int r = lane >> 2;    // 0..7
    const int q = lane & 3;     // 0..3

    float c[2][8][4];
#pragma unroll
    for (int mt = 0; mt < 2; mt++)
#pragma unroll
        for (int nt = 0; nt < 8; nt++)
#pragma unroll
            for (int v = 0; v < 4; v++) c[mt][nt][v] = 0.f;

    int buf = 0;
    loadTile(0);
    storeTile(0);
    __syncthreads();

    const int T = HID / 16;   // 16
    for (int t = 0; t < T; t++) {
        if (t + 1 < T) loadTile((t + 1) * 16);

#pragma unroll
        for (int kb = 0; kb < 16; kb += 8) {
            uint32_t af[2][4];
#pragma unroll
            for (int mt = 0; mt < 2; mt++) {
                int mb = warp_m + mt * 16 + r;
                af[mt][0] = As[buf][kb + q][mb];
                af[mt][1] = As[buf][kb + q][mb + 8];
                af[mt][2] = As[buf][kb + q + 4][mb];
                af[mt][3] = As[buf][kb + q + 4][mb + 8];
            }
            uint32_t bf[8][2];
#pragma unroll
            for (int nt = 0; nt < 8; nt++) {
                int nb = warp_n + nt * 8 + r;
                bf[nt][0] = Bs[buf][kb + q][nb];
                bf[nt][1] = Bs[buf][kb + q + 4][nb];
            }
#pragma unroll
            for (int mt = 0; mt < 2; mt++)
#pragma unroll
                for (int nt = 0; nt < 8; nt++)
                    mma_tf32(c[mt][nt], af[mt][0], af[mt][1], af[mt][2], af[mt][3],
                             bf[nt][0], bf[nt][1]);
        }

        if (t + 1 < T) {
            storeTile(buf ^ 1);
            __syncthreads();
            buf ^= 1;
        }
    }

    // Epilogue: D fragment -> g_PQ. row = m0+warp_m+mt*16+r (+8), col = n0+warp_n+nt*8+2q (+1)
#pragma unroll
    for (int mt = 0; mt < 2; mt++) {
#pragma unroll
        for (int nt = 0; nt < 8; nt++) {
            int row = m0 + warp_m + mt * 16 + r;
            int col = n0 + warp_n + nt * 8 + 2 * q;
            *reinterpret_cast<float2*>(g_PQ + (size_t)row * 512 + col) =
                make_float2(c[mt][nt][0], c[mt][nt][1]);
            *reinterpret_cast<float2*>(g_PQ + (size_t)(row + 8) * 512 + col) =
                make_float2(c[mt][nt][2], c[mt][nt][3]);
        }
    }
}

// ---------------------------------------------------------------------------
// Prefix-mean + bias + relu, fused weight head. Dyn smem 64KB.
// ---------------------------------------------------------------------------
__global__ void prefix_relu_kernel(const float* __restrict__ b_gnn,
                                   const float* __restrict__ Ww) {
    extern __shared__ float sh[];           // [64][256]
    int b = blockIdx.x;
    int f = threadIdx.x;
    float bias = b_gnn[f];
    float run = 0.f;
    const float* Sp  = g_S  + (size_t)b * NND * HID + f;
    const float* Sbp = g_Sb + (size_t)b * NND * HID + f;
    float* Hp = g_H + (size_t)b * NND * HID + f;
#pragma unroll 8
    for (int j = 0; j < NND; j++) {
        float h = ((j == 0) ? 0.f : run / (float)j) + bias;
        h = h > 0.f ? h : 0.f;
        Hp[j * HID] = h;
        sh[j * HID + f] = h;
        run += Sp[j * HID] + Sbp[j * HID];
    }
    __syncthreads();

    int warp = f >> 5, lane = f & 31;
#pragma unroll
    for (int t = 0; t < 8; t++) {
        int j = warp * 8 + t;
        const float* h = sh + j * HID;
        float pw = 0.f, qw = 0.f;
#pragma unroll
        for (int qq = 0; qq < 8; qq++) {
            int k = lane + 32 * qq;
            float hv = h[k];
            pw = fmaf(hv, Ww[k], pw);
            qw = fmaf(hv, Ww[HID + k], qw);
        }
#pragma unroll
        for (int o = 16; o; o >>= 1) {
            pw += __shfl_xor_sync(0xFFFFFFFFu, pw, o);
            qw += __shfl_xor_sync(0xFFFFFFFFu, qw, o);
        }
        if (lane == 0) { g_pw[b * NND + j] = pw; g_qw[b * NND + j] = qw; }
    }
}

// ---------------------------------------------------------------------------
// Edge kernel (unchanged): CTA per graph, 1024 threads, 128KB PQ slab in smem.
// ---------------------------------------------------------------------------
__global__ __launch_bounds__(1024, 1)
void edge_kernel(const float* __restrict__ gum,
                 const float* __restrict__ bm,
                 const float* __restrict__ bv,
                 const float* __restrict__ bw) {
    extern __shared__ float s_pq[];     // 64*512
    __shared__ float s_pw[NND], s_qw[NND], s_bm[OUTD], s_bv[OUTD];
    __shared__ int   s_eij[EPG];

    const int b = blockIdx.x;
    const int tid = threadIdx.x;

    const float4* src = reinterpret_cast<const float4*>(g_PQ + (size_t)b * NND * 512);
    float4* dst = reinterpret_cast<float4*>(s_pq);
    for (int i = tid; i < NND * 512 / 4; i += 1024) dst[i] = src[i];
    if (tid < NND)  { s_pw[tid] = g_pw[b * NND + tid]; s_qw[tid] = g_qw[b * NND + tid]; }
    if (tid < OUTD) { s_bm[tid] = bm[tid]; s_bv[tid] = bv[tid]; }
    for (int i = tid; i < EPG; i += 1024) s_eij[i] = g_eij[i];
    __syncthreads();

    const float bwv = bw[0];
    const int warp = tid >> 5, lane = tid & 31;
    double ssum = 0.0;

    float accSave = 0.f;
    int myE = -1;
    for (int g = 0; g < 63; g++) {
        int e = warp + (g << 5);
        int ij = s_eij[e];
        int i = ij >> 8, j = ij & 255;
        const float* P = s_pq + i * 512;
        const float* Q = s_pq + j * 512;
        float acc = 0.f;
#pragma unroll
        for (int t = 0; t < 4; t++) {
            int k = lane + 32 * t;
            float m   = P[k]       + Q[256 + k] + s_bm[k];
            float xv  = P[128 + k] + Q[384 + k] + s_bv[k];
            float sp  = fmaxf(xv, 0.f) + __logf(1.f + __expf(-fabsf(xv)));
            float var = sp + 1e-6f;
            acc += __fdividef(m * m, var + 1e-8f);
        }
#pragma unroll
        for (int o = 16; o; o >>= 1) acc += __shfl_xor_sync(0xFFFFFFFFu, acc, o);

        int slot = g & 31;
        if (lane == slot) { accSave = acc; myE = e; }

        if (slot == 31 || g == 62) {
            if (myE >= 0) {
                int ij2 = s_eij[myE];
                int ii = ij2 >> 8, jj = ij2 & 255;
                float sim = expf(-0.5f * (accSave * (1.f / OUTD)));
                float wl  = s_pw[ii] + s_qw[jj] + bwv;
                float w   = 1.f / (1.f + expf(-wl));
                float u   = gum[b * EPG + myE];
                float gb  = -logf(-logf(u));
                float z   = (w + gb) * 2.f;     // / TEMPERATURE (0.5)
                float s   = expf(z);
                g_prod[b * EPG + myE] = sim * s;
                ssum += (double)s;
            }
            myE = -1;
        }
    }
#pragma unroll
    for (int o = 16; o; o >>= 1) {
        double other = __shfl_xor_sync(0xFFFFFFFFu, ssum, o);
        ssum += other;
    }
    if (lane == 0) atomicAdd(&g_sum, ssum);
}

__global__ void inv_kernel() { g_inv = (float)(1.0 / g_sum); }

__global__ void out_kernel(float* __restrict__ out) {
    int idx = blockIdx.x * 256 + threadIdx.x;
    int b = idx >> 12;
    int rem = idx & 4095;
    int i = rem >> 6, j = rem & 63;
    float val = 0.f;
    if (i < j) {
        int e = i * (NND - 1) - (i * (i - 1)) / 2 + (j - i - 1);
        val = g_prod[b * EPG + e] * g_inv;
    }
    out[idx] = val;
}

// ---------------------------------------------------------------------------
extern "C" void kernel_launch(void* const* d_in, const int* in_sizes, int n_in,
                              void* d_out, int out_size) {
    // Size-based binding. No __device__ global is ever passed as an arg.
    const float *x_topo = 0, *x_temp = 0, *gum = 0, *W_gnn = 0, *b_gnn = 0;
    const float *W_mean = 0, *b_mean = 0, *W_var = 0, *b_var = 0, *W_w = 0, *b_w = 0;
    for (int k = 0; k < n_in; k++) {
        const float* p = (const float*)d_in[k];
        switch (in_sizes[k]) {
            case 524288:  x_topo = p; break;
            case 2097152: x_temp = p; break;
            case 258048:  gum = p; break;
            case 81920:   W_gnn = p; break;
            case 256:     b_gnn = p; break;
            case 65536:   if (!W_mean) W_mean = p; else W_var = p; break;
            case 128:     if (!b_mean) b_mean = p; else b_var = p; break;
            case 512:     W_w = p; break;
            case 1:       b_w = p; break;
            default: break;
        }
    }
    float* out = (float*)d_out;

    cudaFuncSetAttribute(edge_kernel, cudaFuncAttributeMaxDynamicSharedMemorySize, 131072);
    cudaFuncSetAttribute(prefix_relu_kernel, cudaFuncAttributeMaxDynamicSharedMemorySize, 65536);

    setup_kernel<<<8, 256>>>();

    // S halves = [topo|temp] @ W_gnn   (split-K x2: 256 CTAs)
    { dim3 g(HID / 128, NODES / 128, 2); sgemm1_kernel<<<g, 256>>>(x_topo, x_temp, W_gnn); }

    // H = relu(prefix-mean(S + Sb) + b), fused whead
    prefix_relu_kernel<<<BGR, HID, 65536>>>(b_gnn, W_w);

    // PQ = H @ WB(virtual) via mma.sync tf32  (grid 4 x 64 = 256 CTAs)
    { dim3 g(4, NODES / 128); sgemm2_mma_kernel<<<g, 256>>>(W_mean, W_var); }

    edge_kernel<<<BGR, 1024, 131072>>>(gum, b_mean, b_var, b_w);

    inv_kernel<<<1, 1>>>();

    out_kernel<<<(BGR * NND * NND) / 256, 256>>>(out);
}